// round 8
// baseline (speedup 1.0000x reference)
#include <cuda_runtime.h>
#include <cstdint>

// B=16, N=3136 (56x56), C=384, NH=12, hd=32, WS=7, nW=1024, S=49.
#define M_TOK   50176
#define C_DIM   384
#define QKV_DIM 1152
#define K_DIM   384

// Scratch (device globals: allocation-free)
static __device__ float g_x  [(size_t)M_TOK * C_DIM];
static __device__ float g_qkv[(size_t)M_TOK * QKV_DIM];
static __device__ float g_att[(size_t)M_TOK * C_DIM];
static __device__ float g_wqkv[QKV_DIM * C_DIM];
static __device__ float g_wproj[C_DIM * C_DIM];

__device__ __forceinline__ float tf32r(float x) {
    uint32_t u;
    asm("cvt.rna.tf32.f32 %0, %1;" : "=r"(u) : "f"(x));
    return __uint_as_float(u);
}

__device__ __forceinline__ void mma_tf32(float c[4],
                                         uint32_t a0, uint32_t a1, uint32_t a2, uint32_t a3,
                                         uint32_t b0, uint32_t b1) {
    asm volatile(
        "mma.sync.aligned.m16n8k8.row.col.f32.tf32.tf32.f32 "
        "{%0,%1,%2,%3}, {%4,%5,%6,%7}, {%8,%9}, {%0,%1,%2,%3};\n"
        : "+f"(c[0]), "+f"(c[1]), "+f"(c[2]), "+f"(c[3])
        : "r"(a0), "r"(a1), "r"(a2), "r"(a3), "r"(b0), "r"(b1));
}

__device__ __forceinline__ void ldm_x4(uint32_t& d0, uint32_t& d1, uint32_t& d2, uint32_t& d3,
                                       uint32_t addr) {
    asm volatile("ldmatrix.sync.aligned.m8n8.x4.shared.b16 {%0,%1,%2,%3}, [%4];"
                 : "=r"(d0), "=r"(d1), "=r"(d2), "=r"(d3) : "r"(addr));
}

__device__ __forceinline__ void cp16(uint32_t smem_addr, const float* gptr) {
    asm volatile("cp.async.cg.shared.global [%0], [%1], 16;\n"
                 :: "r"(smem_addr), "l"(gptr));
}

// ---------------------------------------------------------------------------
// Prepass: elementwise tf32 rounding (float4 streaming)
// ---------------------------------------------------------------------------
__global__ void cvt_kernel(const float* __restrict__ src, float* __restrict__ dst, int n4)
{
    int i = blockIdx.x * blockDim.x + threadIdx.x;
    if (i < n4) {
        float4 v = reinterpret_cast<const float4*>(src)[i];
        v.x = tf32r(v.x); v.y = tf32r(v.y); v.z = tf32r(v.z); v.w = tf32r(v.w);
        reinterpret_cast<float4*>(dst)[i] = v;
    }
}

// ---------------------------------------------------------------------------
// GEMM:  C[m,n] = sum_k A[m,k]*B[n,k] (+bias[n]).  A,B pre-rounded to tf32.
// BM=128, BN=128, BK=32, 3-stage cp.async pipeline, stride-36 padded smem.
// ONE __syncthreads per K-iter (wait -> sync -> issue -> compute).
// A fragments for the whole BK block hoisted before the kk loop so B loads
// of step kk+1 overlap the MMAs of step kk.
// ---------------------------------------------------------------------------
#define STAGE_F (128 * 36 * 2)                 // floats per stage (A + B tile)
#define SMEM_BYTES (3 * STAGE_F * 4)           // 110592 -> 2 CTAs/SM

template<bool HAS_BIAS>
__global__ __launch_bounds__(256, 2) void gemm_tn_kernel(
    const float* __restrict__ A, const float* __restrict__ B,
    const float* __restrict__ bias, float* __restrict__ Cout, int N)
{
    extern __shared__ float smem[];

    const int tid  = threadIdx.x;
    const int lane = tid & 31;
    const int warp = tid >> 5;
    const int wm   = warp & 3;          // 0..3 along M
    const int wn   = warp >> 2;         // 0..1 along N
    const int g    = lane >> 2;
    const int t4   = lane & 3;

    const long bm = (long)blockIdx.y * 128;
    const long bn = (long)blockIdx.x * 128;

    const int lr = tid >> 3;            // 0..31
    const int lc = (tid & 7) << 2;      // 0,4,..,28

    float acc[2][8][4];
    #pragma unroll
    for (int i = 0; i < 2; i++)
        #pragma unroll
        for (int j = 0; j < 8; j++)
            #pragma unroll
            for (int k = 0; k < 4; k++) acc[i][j][k] = 0.f;

    const float* gA = A + (bm + lr) * (long)K_DIM + lc;
    const float* gB = B + (bn + lr) * (long)K_DIM + lc;

    auto issue = [&](int stg, int kb) {
        float* dA = smem + stg * STAGE_F;
        float* dB = dA + 128 * 36;
        #pragma unroll
        for (int i = 0; i < 4; i++)
            cp16((uint32_t)__cvta_generic_to_shared(dA + (lr + i * 32) * 36 + lc),
                 gA + (long)i * 32 * K_DIM + kb);
        #pragma unroll
        for (int i = 0; i < 4; i++)
            cp16((uint32_t)__cvta_generic_to_shared(dB + (lr + i * 32) * 36 + lc),
                 gB + (long)i * 32 * K_DIM + kb);
        asm volatile("cp.async.commit_group;\n");
    };

    // per-lane ldmatrix base offsets (bytes within a stage's A / B tile)
    const int mi = lane >> 3, ri = lane & 7;
    const uint32_t aOff = ((wm * 32 + ((mi & 1) << 3) + ri) * 36 + ((mi >> 1) << 2)) * 4;
    uint32_t bOff[4];
    #pragma unroll
    for (int p = 0; p < 4; p++)
        bOff[p] = ((wn * 64 + p * 16 + ((mi >> 1) << 3) + ri) * 36 + ((mi & 1) << 2)) * 4;

    const uint32_t sbase = (uint32_t)__cvta_generic_to_shared(smem);

    issue(0, 0);
    issue(1, 32);

    for (int k = 0; k < 12; k++) {
        if (k < 10) asm volatile("cp.async.wait_group 1;\n");
        else        asm volatile("cp.async.wait_group 0;\n");
        __syncthreads();                 // single barrier per iteration

        if (k + 2 < 12) issue((k + 2) % 3, (k + 2) * 32);

        const uint32_t stA = sbase + (k % 3) * (STAGE_F * 4);
        const uint32_t stB = stA + 128 * 36 * 4;

        // hoist all A fragments for this BK=32 block (8 x ldmatrix.x4)
        uint32_t a[4][2][4];
        #pragma unroll
        for (int kq = 0; kq < 4; kq++)
            #pragma unroll
            for (int mt = 0; mt < 2; mt++)
                ldm_x4(a[kq][mt][0], a[kq][mt][1], a[kq][mt][2], a[kq][mt][3],
                       stA + aOff + mt * (16 * 144) + kq * 32);

        #pragma unroll
        for (int kq = 0; kq < 4; kq++) {
            uint32_t bf[8][2];
            #pragma unroll
            for (int p = 0; p < 4; p++) {
                uint32_t d0, d1, d2, d3;
                ldm_x4(d0, d1, d2, d3, stB + bOff[p] + kq * 32);
                bf[2 * p    ][0] = d0; bf[2 * p    ][1] = d1;
                bf[2 * p + 1][0] = d2; bf[2 * p + 1][1] = d3;
            }
            #pragma unroll
            for (int mt = 0; mt < 2; mt++)
                #pragma unroll
                for (int nt = 0; nt < 8; nt++)
                    mma_tf32(acc[mt][nt], a[kq][mt][0], a[kq][mt][1],
                             a[kq][mt][2], a[kq][mt][3], bf[nt][0], bf[nt][1]);
        }
    }
    __syncthreads();   // protect smem reuse before epilogue? (none) -- keep warps together

    #pragma unroll
    for (int mt = 0; mt < 2; mt++) {
        #pragma unroll
        for (int nt = 0; nt < 8; nt++) {
            long row = bm + wm * 32 + mt * 16 + g;
            long col = bn + wn * 64 + nt * 8 + 2 * t4;
            float b0 = 0.f, b1 = 0.f;
            if (HAS_BIAS) { b0 = bias[col]; b1 = bias[col + 1]; }
            *reinterpret_cast<float2*>(Cout + row * (long)N + col) =
                make_float2(acc[mt][nt][0] + b0, acc[mt][nt][1] + b1);
            *reinterpret_cast<float2*>(Cout + (row + 8) * (long)N + col) =
                make_float2(acc[mt][nt][2] + b0, acc[mt][nt][3] + b1);
        }
    }
}

// ---------------------------------------------------------------------------
// Windowed attention (unchanged): one CTA per (head, window). S=49 pad 64.
// ---------------------------------------------------------------------------
__global__ __launch_bounds__(256) void attn_kernel()
{
    __shared__ float qs[64][36];
    __shared__ float ks[64][36];
    __shared__ float vT[32][68];
    __shared__ float ps[64][68];

    const int tid  = threadIdx.x;
    const int lane = tid & 31;
    const int warp = tid >> 5;
    const int g    = lane >> 2;
    const int t4   = lane & 3;

    const int h = blockIdx.x;
    const int w = blockIdx.y;
    const int b   = w >> 6;
    const int whh = (w >> 3) & 7;
    const int ww  = w & 7;
    const int tbase = b * 3136 + whh * 392 + ww * 7;
    const float scale = 0.17677669529663687f;   // 1/sqrt(32)

    for (int i = tid; i < 32 * 16; i += 256) {
        int d = i >> 4, c = 49 + (i & 15);
        vT[d][c] = 0.f;
    }

    for (int idx = tid; idx < 392; idx += 256) {
        int s = idx >> 3, dd = (idx & 7) << 2;
        int tok = tbase + (s / 7) * 56 + (s % 7);
        const float* p = g_qkv + (long)tok * QKV_DIM + h * 32 + dd;
        float4 q4 = *reinterpret_cast<const float4*>(p);
        float4 k4 = *reinterpret_cast<const float4*>(p + 384);
        float4 v4 = *reinterpret_cast<const float4*>(p + 768);
        qs[s][dd    ] = tf32r(q4.x * scale);
        qs[s][dd + 1] = tf32r(q4.y * scale);
        qs[s][dd + 2] = tf32r(q4.z * scale);
        qs[s][dd + 3] = tf32r(q4.w * scale);
        ks[s][dd    ] = tf32r(k4.x);
        ks[s][dd + 1] = tf32r(k4.y);
        ks[s][dd + 2] = tf32r(k4.z);
        ks[s][dd + 3] = tf32r(k4.w);
        vT[dd    ][s] = tf32r(v4.x);
        vT[dd + 1][s] = tf32r(v4.y);
        vT[dd + 2][s] = tf32r(v4.z);
        vT[dd + 3][s] = tf32r(v4.w);
    }
    __syncthreads();

    {
        float acc[4][4];
        #pragma unroll
        for (int j = 0; j < 4; j++)
            #pragma unroll
            for (int k = 0; k < 4; k++) acc[j][k] = 0.f;

        const int m = (warp & 3) * 16;
        #pragma unroll
        for (int kk = 0; kk < 32; kk += 8) {
            uint32_t a0 = __float_as_uint(qs[m + g    ][kk + t4    ]);
            uint32_t a1 = __float_as_uint(qs[m + g + 8][kk + t4    ]);
            uint32_t a2 = __float_as_uint(qs[m + g    ][kk + t4 + 4]);
            uint32_t a3 = __float_as_uint(qs[m + g + 8][kk + t4 + 4]);
            #pragma unroll
            for (int nt = 0; nt < 4; nt++) {
                int n = (warp >> 2) * 32 + nt * 8;
                uint32_t b0 = __float_as_uint(ks[n + g][kk + t4    ]);
                uint32_t b1 = __float_as_uint(ks[n + g][kk + t4 + 4]);
                mma_tf32(acc[nt], a0, a1, a2, a3, b0, b1);
            }
        }
        #pragma unroll
        for (int nt = 0; nt < 4; nt++) {
            int row = (warp & 3) * 16 + g;
            int col = (warp >> 2) * 32 + nt * 8 + 2 * t4;
            *reinterpret_cast<float2*>(&ps[row][col])     = make_float2(acc[nt][0], acc[nt][1]);
            *reinterpret_cast<float2*>(&ps[row + 8][col]) = make_float2(acc[nt][2], acc[nt][3]);
        }
    }
    __syncthreads();

    for (int r = warp; r < 49; r += 8) {
        float s0 = ps[r][lane];
        float s1 = ps[r][lane + 32];
        bool  v1 = (lane + 32) < 49;
        float mx = fmaxf(s0, v1 ? s1 : -1e30f);
        #pragma unroll
        for (int o = 16; o; o >>= 1) mx = fmaxf(mx, __shfl_xor_sync(0xffffffffu, mx, o));
        float e0 = __expf(s0 - mx);
        float e1 = v1 ? __expf(s1 - mx) : 0.f;
        float sm = e0 + e1;
        #pragma unroll
        for (int o = 16; o; o >>= 1) sm += __shfl_xor_sync(0xffffffffu, sm, o);
        float inv = 1.f / sm;
        ps[r][lane]      = tf32r(e0 * inv);
        ps[r][lane + 32] = tf32r(e1 * inv);
    }
    __syncthreads();

    {
        float acc[2][4];
        #pragma unroll
        for (int j = 0; j < 2; j++)
            #pragma unroll
            for (int k = 0; k < 4; k++) acc[j][k] = 0.f;

        const int m = (warp & 3) * 16;
        #pragma unroll
        for (int kk = 0; kk < 64; kk += 8) {
            uint32_t a0 = __float_as_uint(ps[m + g    ][kk + t4    ]);
            uint32_t a1 = __float_as_uint(ps[m + g + 8][kk + t4    ]);
            uint32_t a2 = __float_as_uint(ps[m + g    ][kk + t4 + 4]);
            uint32_t a3 = __float_as_uint(ps[m + g + 8][kk + t4 + 4]);
            #pragma unroll
            for (int j = 0; j < 2; j++) {
                int n = (warp >> 2) * 16 + j * 8;
                uint32_t b0 = __float_as_uint(vT[n + g][kk + t4    ]);
                uint32_t b1 = __float_as_uint(vT[n + g][kk + t4 + 4]);
                mma_tf32(acc[j], a0, a1, a2, a3, b0, b1);
            }
        }
        #pragma unroll
        for (int j = 0; j < 2; j++) {
            int col = (warp >> 2) * 16 + j * 8 + 2 * t4;
            #pragma unroll
            for (int i = 0; i < 2; i++) {
                int r = m + g + i * 8;
                if (r < 49) {
                    int tok = tbase + (r / 7) * 56 + (r % 7);
                    *reinterpret_cast<float2*>(g_att + (long)tok * C_DIM + h * 32 + col) =
                        make_float2(tf32r(acc[j][0 + 2 * i]), tf32r(acc[j][1 + 2 * i]));
                }
            }
        }
    }
}

// ---------------------------------------------------------------------------
extern "C" void kernel_launch(void* const* d_in, const int* in_sizes, int n_in,
                              void* d_out, int out_size)
{
    const float* x      = (const float*)d_in[0];
    const float* w_qkv  = (const float*)d_in[1];
    const float* w_proj = (const float*)d_in[2];
    const float* b_proj = (const float*)d_in[3];
    float* out = (float*)d_out;

    float *xp, *qkvp, *attp, *wqkvp, *wprojp;
    cudaGetSymbolAddress((void**)&xp,     g_x);
    cudaGetSymbolAddress((void**)&qkvp,   g_qkv);
    cudaGetSymbolAddress((void**)&attp,   g_att);
    cudaGetSymbolAddress((void**)&wqkvp,  g_wqkv);
    cudaGetSymbolAddress((void**)&wprojp, g_wproj);

    cudaFuncSetAttribute(gemm_tn_kernel<false>,
                         cudaFuncAttributeMaxDynamicSharedMemorySize, SMEM_BYTES);
    cudaFuncSetAttribute(gemm_tn_kernel<true>,
                         cudaFuncAttributeMaxDynamicSharedMemorySize, SMEM_BYTES);

    // 0) tf32-rounding prepass
    cvt_kernel<<<(M_TOK * C_DIM / 4) / 256, 256>>>(x, xp, M_TOK * C_DIM / 4);
    cvt_kernel<<<(QKV_DIM * C_DIM / 4 + 255) / 256, 256>>>(w_qkv, wqkvp, QKV_DIM * C_DIM / 4);
    cvt_kernel<<<(C_DIM * C_DIM / 4 + 255) / 256, 256>>>(w_proj, wprojp, C_DIM * C_DIM / 4);

    // 1) QKV projection: [50176 x 384] @ [384 x 1152]
    gemm_tn_kernel<false><<<dim3(QKV_DIM / 128, M_TOK / 128), 256, SMEM_BYTES>>>(
        xp, wqkvp, nullptr, qkvp, QKV_DIM);

    // 2) Windowed attention
    attn_kernel<<<dim3(12, 1024), 256>>>();

    // 3) Output projection + bias: [50176 x 384] @ [384 x 384]
    gemm_tn_kernel<true><<<dim3(C_DIM / 128, M_TOK / 128), 256, SMEM_BYTES>>>(
        attp, wprojp, b_proj, out, C_DIM);
}

// round 9
// speedup vs baseline: 1.0079x; 1.0079x over previous
#include <cuda_runtime.h>
#include <cstdint>

// B=16, N=3136 (56x56), C=384, NH=12, hd=32, WS=7, nW=1024, S=49.
#define M_TOK   50176
#define C_DIM   384
#define QKV_DIM 1152
#define K_DIM   384

// Scratch (device globals: allocation-free)
static __device__ float g_x  [(size_t)M_TOK * C_DIM];
// window-major qkv: [w][qkv][h][s][d] -> ((w*3+qkv)*12+h)*1568 + s*32 + d
static __device__ float g_qkv[(size_t)M_TOK * QKV_DIM];
// window-major attn out: row = w*49+s, 384 cols
static __device__ float g_att[(size_t)M_TOK * C_DIM];
static __device__ float g_wqkv[QKV_DIM * C_DIM];
static __device__ float g_wproj[C_DIM * C_DIM];

__device__ __forceinline__ float tf32r(float x) {
    uint32_t u;
    asm("cvt.rna.tf32.f32 %0, %1;" : "=r"(u) : "f"(x));
    return __uint_as_float(u);
}

__device__ __forceinline__ void mma_tf32(float c[4],
                                         uint32_t a0, uint32_t a1, uint32_t a2, uint32_t a3,
                                         uint32_t b0, uint32_t b1) {
    asm volatile(
        "mma.sync.aligned.m16n8k8.row.col.f32.tf32.tf32.f32 "
        "{%0,%1,%2,%3}, {%4,%5,%6,%7}, {%8,%9}, {%0,%1,%2,%3};\n"
        : "+f"(c[0]), "+f"(c[1]), "+f"(c[2]), "+f"(c[3])
        : "r"(a0), "r"(a1), "r"(a2), "r"(a3), "r"(b0), "r"(b1));
}

__device__ __forceinline__ void ldm_x4(uint32_t& d0, uint32_t& d1, uint32_t& d2, uint32_t& d3,
                                       uint32_t addr) {
    asm volatile("ldmatrix.sync.aligned.m8n8.x4.shared.b16 {%0,%1,%2,%3}, [%4];"
                 : "=r"(d0), "=r"(d1), "=r"(d2), "=r"(d3) : "r"(addr));
}

__device__ __forceinline__ void cp16(uint32_t smem_addr, const float* gptr) {
    asm volatile("cp.async.cg.shared.global [%0], [%1], 16;\n"
                 :: "r"(smem_addr), "l"(gptr));
}

// ---------------------------------------------------------------------------
// Prepass: elementwise tf32 rounding (float4 streaming)
// ---------------------------------------------------------------------------
__global__ void cvt_kernel(const float* __restrict__ src, float* __restrict__ dst, int n4)
{
    int i = blockIdx.x * blockDim.x + threadIdx.x;
    if (i < n4) {
        float4 v = reinterpret_cast<const float4*>(src)[i];
        v.x = tf32r(v.x); v.y = tf32r(v.y); v.z = tf32r(v.z); v.w = tf32r(v.w);
        reinterpret_cast<float4*>(dst)[i] = v;
    }
}

// ---------------------------------------------------------------------------
// GEMM:  C[m,n] = sum_k A[m,k]*B[n,k].  A,B pre-rounded to tf32.
// BM=128, BN=128, BK=32, 3-stage cp.async, stride-36 padded smem,
// ldmatrix fragments. MODE selects the epilogue:
//   MODE 0: plain row-major store (unused)
//   MODE 1: scatter into window-major qkv layout          (QKV proj)
//   MODE 2: un-permute window-major rows -> token rows, +bias (out proj)
// ---------------------------------------------------------------------------
#define STAGE_F (128 * 36 * 2)
#define SMEM_BYTES (3 * STAGE_F * 4)           // 110592 -> 2 CTAs/SM

template<int MODE>
__global__ __launch_bounds__(256, 2) void gemm_tn_kernel(
    const float* __restrict__ A, const float* __restrict__ B,
    const float* __restrict__ bias, float* __restrict__ Cout, int N)
{
    extern __shared__ float smem[];

    const int tid  = threadIdx.x;
    const int lane = tid & 31;
    const int warp = tid >> 5;
    const int wm   = warp & 3;
    const int wn   = warp >> 2;
    const int g    = lane >> 2;
    const int t4   = lane & 3;

    const long bm = (long)blockIdx.y * 128;
    const long bn = (long)blockIdx.x * 128;

    const int lr = tid >> 3;
    const int lc = (tid & 7) << 2;

    float acc[2][8][4];
    #pragma unroll
    for (int i = 0; i < 2; i++)
        #pragma unroll
        for (int j = 0; j < 8; j++)
            #pragma unroll
            for (int k = 0; k < 4; k++) acc[i][j][k] = 0.f;

    const float* gA = A + (bm + lr) * (long)K_DIM + lc;
    const float* gB = B + (bn + lr) * (long)K_DIM + lc;

    auto issue = [&](int stg, int kb) {
        float* dA = smem + stg * STAGE_F;
        float* dB = dA + 128 * 36;
        #pragma unroll
        for (int i = 0; i < 4; i++)
            cp16((uint32_t)__cvta_generic_to_shared(dA + (lr + i * 32) * 36 + lc),
                 gA + (long)i * 32 * K_DIM + kb);
        #pragma unroll
        for (int i = 0; i < 4; i++)
            cp16((uint32_t)__cvta_generic_to_shared(dB + (lr + i * 32) * 36 + lc),
                 gB + (long)i * 32 * K_DIM + kb);
        asm volatile("cp.async.commit_group;\n");
    };

    const int mi = lane >> 3, ri = lane & 7;
    const uint32_t aOff = ((wm * 32 + ((mi & 1) << 3) + ri) * 36 + ((mi >> 1) << 2)) * 4;
    uint32_t bOff[4];
    #pragma unroll
    for (int p = 0; p < 4; p++)
        bOff[p] = ((wn * 64 + p * 16 + ((mi >> 1) << 3) + ri) * 36 + ((mi & 1) << 2)) * 4;

    const uint32_t sbase = (uint32_t)__cvta_generic_to_shared(smem);

    issue(0, 0);
    issue(1, 32);

    for (int k = 0; k < 12; k++) {
        if (k < 10) asm volatile("cp.async.wait_group 1;\n");
        else        asm volatile("cp.async.wait_group 0;\n");
        __syncthreads();

        if (k + 2 < 12) issue((k + 2) % 3, (k + 2) * 32);

        const uint32_t stA = sbase + (k % 3) * (STAGE_F * 4);
        const uint32_t stB = stA + 128 * 36 * 4;

        uint32_t a[4][2][4];
        #pragma unroll
        for (int kq = 0; kq < 4; kq++)
            #pragma unroll
            for (int mt = 0; mt < 2; mt++)
                ldm_x4(a[kq][mt][0], a[kq][mt][1], a[kq][mt][2], a[kq][mt][3],
                       stA + aOff + mt * (16 * 144) + kq * 32);

        #pragma unroll
        for (int kq = 0; kq < 4; kq++) {
            uint32_t bf[8][2];
            #pragma unroll
            for (int p = 0; p < 4; p++) {
                uint32_t d0, d1, d2, d3;
                ldm_x4(d0, d1, d2, d3, stB + bOff[p] + kq * 32);
                bf[2 * p    ][0] = d0; bf[2 * p    ][1] = d1;
                bf[2 * p + 1][0] = d2; bf[2 * p + 1][1] = d3;
            }
            #pragma unroll
            for (int mt = 0; mt < 2; mt++)
                #pragma unroll
                for (int nt = 0; nt < 8; nt++)
                    mma_tf32(acc[mt][nt], a[kq][mt][0], a[kq][mt][1],
                             a[kq][mt][2], a[kq][mt][3], bf[nt][0], bf[nt][1]);
        }
    }

    // ---- epilogue ----
    #pragma unroll
    for (int mt = 0; mt < 2; mt++) {
        #pragma unroll
        for (int half = 0; half < 2; half++) {
            long row = bm + wm * 32 + mt * 16 + g + half * 8;

            if (MODE == 1) {
                // token row -> (window, slot)
                int t  = (int)row;
                int b  = t / 3136;
                int r2 = t - b * 3136;
                int rr = r2 / 56;
                int cc = r2 - rr * 56;
                int w  = b * 64 + (rr / 7) * 8 + (cc / 7);
                int s  = (rr % 7) * 7 + (cc % 7);
                #pragma unroll
                for (int nt = 0; nt < 8; nt++) {
                    int col = (int)bn + wn * 64 + nt * 8 + 2 * t4;
                    int qkv = col / 384;
                    int rem = col - qkv * 384;
                    int h   = rem >> 5;
                    int d   = rem & 31;
                    long off = (long)((w * 3 + qkv) * 12 + h) * 1568 + s * 32 + d;
                    *reinterpret_cast<float2*>(Cout + off) =
                        make_float2(acc[mt][nt][2 * half], acc[mt][nt][2 * half + 1]);
                }
            } else if (MODE == 2) {
                // window-major row -> token row
                int r = (int)row;
                int w = r / 49;
                int s = r - w * 49;
                int b  = w >> 6;
                int wh = (w >> 3) & 7;
                int ww = w & 7;
                long tok = (long)b * 3136 + (wh * 7 + s / 7) * 56 + ww * 7 + (s % 7);
                #pragma unroll
                for (int nt = 0; nt < 8; nt++) {
                    long col = bn + wn * 64 + nt * 8 + 2 * t4;
                    float2 bv = *reinterpret_cast<const float2*>(bias + col);
                    *reinterpret_cast<float2*>(Cout + tok * (long)N + col) =
                        make_float2(acc[mt][nt][2 * half] + bv.x,
                                    acc[mt][nt][2 * half + 1] + bv.y);
                }
            } else {
                #pragma unroll
                for (int nt = 0; nt < 8; nt++) {
                    long col = bn + wn * 64 + nt * 8 + 2 * t4;
                    *reinterpret_cast<float2*>(Cout + row * (long)N + col) =
                        make_float2(acc[mt][nt][2 * half], acc[mt][nt][2 * half + 1]);
                }
            }
        }
    }
}

// ---------------------------------------------------------------------------
// Windowed attention: one CTA per (head, window). S=49 padded to 64, hd=32.
// Q/K/V now contiguous per (w,h): ((w*3+qkv)*12+h)*1568 + s*32+d.
// Output rows window-major: g_att[(w*49+s)*384 + h*32 + col].
// ---------------------------------------------------------------------------
__global__ __launch_bounds__(256) void attn_kernel()
{
    __shared__ float qs[64][36];
    __shared__ float ks[64][36];
    __shared__ float vT[32][68];
    __shared__ float ps[64][68];

    const int tid  = threadIdx.x;
    const int lane = tid & 31;
    const int warp = tid >> 5;
    const int g    = lane >> 2;
    const int t4   = lane & 3;

    const int h = blockIdx.x;
    const int w = blockIdx.y;
    const float scale = 0.17677669529663687f;   // 1/sqrt(32)

    const float* qb = g_qkv + (long)((w * 3 + 0) * 12 + h) * 1568;
    const float* kb = g_qkv + (long)((w * 3 + 1) * 12 + h) * 1568;
    const float* vb = g_qkv + (long)((w * 3 + 2) * 12 + h) * 1568;

    for (int i = tid; i < 32 * 16; i += 256) {
        int d = i >> 4, c = 49 + (i & 15);
        vT[d][c] = 0.f;
    }

    // fully coalesced float4 loads (1568 floats = 392 float4 per matrix)
    for (int idx = tid; idx < 392; idx += 256) {
        int s = idx >> 3, dd = (idx & 7) << 2;
        float4 q4 = *reinterpret_cast<const float4*>(qb + idx * 4);
        float4 k4 = *reinterpret_cast<const float4*>(kb + idx * 4);
        float4 v4 = *reinterpret_cast<const float4*>(vb + idx * 4);
        qs[s][dd    ] = tf32r(q4.x * scale);
        qs[s][dd + 1] = tf32r(q4.y * scale);
        qs[s][dd + 2] = tf32r(q4.z * scale);
        qs[s][dd + 3] = tf32r(q4.w * scale);
        ks[s][dd    ] = tf32r(k4.x);
        ks[s][dd + 1] = tf32r(k4.y);
        ks[s][dd + 2] = tf32r(k4.z);
        ks[s][dd + 3] = tf32r(k4.w);
        vT[dd    ][s] = tf32r(v4.x);
        vT[dd + 1][s] = tf32r(v4.y);
        vT[dd + 2][s] = tf32r(v4.z);
        vT[dd + 3][s] = tf32r(v4.w);
    }
    __syncthreads();

    {
        float acc[4][4];
        #pragma unroll
        for (int j = 0; j < 4; j++)
            #pragma unroll
            for (int k = 0; k < 4; k++) acc[j][k] = 0.f;

        const int m = (warp & 3) * 16;
        #pragma unroll
        for (int kk = 0; kk < 32; kk += 8) {
            uint32_t a0 = __float_as_uint(qs[m + g    ][kk + t4    ]);
            uint32_t a1 = __float_as_uint(qs[m + g + 8][kk + t4    ]);
            uint32_t a2 = __float_as_uint(qs[m + g    ][kk + t4 + 4]);
            uint32_t a3 = __float_as_uint(qs[m + g + 8][kk + t4 + 4]);
            #pragma unroll
            for (int nt = 0; nt < 4; nt++) {
                int n = (warp >> 2) * 32 + nt * 8;
                uint32_t b0 = __float_as_uint(ks[n + g][kk + t4    ]);
                uint32_t b1 = __float_as_uint(ks[n + g][kk + t4 + 4]);
                mma_tf32(acc[nt], a0, a1, a2, a3, b0, b1);
            }
        }
        #pragma unroll
        for (int nt = 0; nt < 4; nt++) {
            int row = (warp & 3) * 16 + g;
            int col = (warp >> 2) * 32 + nt * 8 + 2 * t4;
            *reinterpret_cast<float2*>(&ps[row][col])     = make_float2(acc[nt][0], acc[nt][1]);
            *reinterpret_cast<float2*>(&ps[row + 8][col]) = make_float2(acc[nt][2], acc[nt][3]);
        }
    }
    __syncthreads();

    for (int r = warp; r < 49; r += 8) {
        float s0 = ps[r][lane];
        float s1 = ps[r][lane + 32];
        bool  v1 = (lane + 32) < 49;
        float mx = fmaxf(s0, v1 ? s1 : -1e30f);
        #pragma unroll
        for (int o = 16; o; o >>= 1) mx = fmaxf(mx, __shfl_xor_sync(0xffffffffu, mx, o));
        float e0 = __expf(s0 - mx);
        float e1 = v1 ? __expf(s1 - mx) : 0.f;
        float sm = e0 + e1;
        #pragma unroll
        for (int o = 16; o; o >>= 1) sm += __shfl_xor_sync(0xffffffffu, sm, o);
        float inv = 1.f / sm;
        ps[r][lane]      = tf32r(e0 * inv);
        ps[r][lane + 32] = tf32r(e1 * inv);
    }
    __syncthreads();

    {
        float acc[2][4];
        #pragma unroll
        for (int j = 0; j < 2; j++)
            #pragma unroll
            for (int k = 0; k < 4; k++) acc[j][k] = 0.f;

        const int m = (warp & 3) * 16;
        #pragma unroll
        for (int kk = 0; kk < 64; kk += 8) {
            uint32_t a0 = __float_as_uint(ps[m + g    ][kk + t4    ]);
            uint32_t a1 = __float_as_uint(ps[m + g + 8][kk + t4    ]);
            uint32_t a2 = __float_as_uint(ps[m + g    ][kk + t4 + 4]);
            uint32_t a3 = __float_as_uint(ps[m + g + 8][kk + t4 + 4]);
            #pragma unroll
            for (int j = 0; j < 2; j++) {
                int n = (warp >> 2) * 16 + j * 8;
                uint32_t b0 = __float_as_uint(vT[n + g][kk + t4    ]);
                uint32_t b1 = __float_as_uint(vT[n + g][kk + t4 + 4]);
                mma_tf32(acc[j], a0, a1, a2, a3, b0, b1);
            }
        }
        #pragma unroll
        for (int j = 0; j < 2; j++) {
            int col = (warp >> 2) * 16 + j * 8 + 2 * t4;
            #pragma unroll
            for (int i = 0; i < 2; i++) {
                int r = m + g + i * 8;
                if (r < 49) {
                    long off = (long)(w * 49 + r) * C_DIM + h * 32 + col;
                    *reinterpret_cast<float2*>(g_att + off) =
                        make_float2(tf32r(acc[j][0 + 2 * i]), tf32r(acc[j][1 + 2 * i]));
                }
            }
        }
    }
}

// ---------------------------------------------------------------------------
extern "C" void kernel_launch(void* const* d_in, const int* in_sizes, int n_in,
                              void* d_out, int out_size)
{
    const float* x      = (const float*)d_in[0];
    const float* w_qkv  = (const float*)d_in[1];
    const float* w_proj = (const float*)d_in[2];
    const float* b_proj = (const float*)d_in[3];
    float* out = (float*)d_out;

    float *xp, *qkvp, *attp, *wqkvp, *wprojp;
    cudaGetSymbolAddress((void**)&xp,     g_x);
    cudaGetSymbolAddress((void**)&qkvp,   g_qkv);
    cudaGetSymbolAddress((void**)&attp,   g_att);
    cudaGetSymbolAddress((void**)&wqkvp,  g_wqkv);
    cudaGetSymbolAddress((void**)&wprojp, g_wproj);

    cudaFuncSetAttribute(gemm_tn_kernel<1>,
                         cudaFuncAttributeMaxDynamicSharedMemorySize, SMEM_BYTES);
    cudaFuncSetAttribute(gemm_tn_kernel<2>,
                         cudaFuncAttributeMaxDynamicSharedMemorySize, SMEM_BYTES);

    // 0) tf32-rounding prepass
    cvt_kernel<<<(M_TOK * C_DIM / 4) / 256, 256>>>(x, xp, M_TOK * C_DIM / 4);
    cvt_kernel<<<(QKV_DIM * C_DIM / 4 + 255) / 256, 256>>>(w_qkv, wqkvp, QKV_DIM * C_DIM / 4);
    cvt_kernel<<<(C_DIM * C_DIM / 4 + 255) / 256, 256>>>(w_proj, wprojp, C_DIM * C_DIM / 4);

    // 1) QKV projection -> window-major qkv layout
    gemm_tn_kernel<1><<<dim3(QKV_DIM / 128, M_TOK / 128), 256, SMEM_BYTES>>>(
        xp, wqkvp, nullptr, qkvp, QKV_DIM);

    // 2) Windowed attention (coalesced loads, window-major output rows)
    attn_kernel<<<dim3(12, 1024), 256>>>();

    // 3) Output projection + bias; rows un-permuted back to token order
    gemm_tn_kernel<2><<<dim3(C_DIM / 128, M_TOK / 128), 256, SMEM_BYTES>>>(
        attp, wprojp, b_proj, out, C_DIM);
}

// round 10
// speedup vs baseline: 1.1971x; 1.1878x over previous
#include <cuda_runtime.h>
#include <cuda_fp16.h>
#include <cstdint>

// B=16, N=3136 (56x56), C=384, NH=12, hd=32, WS=7, nW=1024, S=49.
#define M_TOK   50176
#define C_DIM   384
#define QKV_DIM 1152
#define K_DIM   384

// Scratch (device globals: allocation-free)
static __device__ __half g_xh  [(size_t)M_TOK * C_DIM];      // fp16 x
static __device__ __half g_wqkvh[QKV_DIM * C_DIM];           // fp16 weights
static __device__ __half g_wprojh[C_DIM * C_DIM];
// window-major qkv (f32): ((w*3+qkv)*12+h)*1568 + s*32 + d
static __device__ float  g_qkv[(size_t)M_TOK * QKV_DIM];
// window-major attn out (fp16): row = w*49+s, 384 cols
static __device__ __half g_att[(size_t)M_TOK * C_DIM];

__device__ __forceinline__ float tf32r(float x) {
    uint32_t u;
    asm("cvt.rna.tf32.f32 %0, %1;" : "=r"(u) : "f"(x));
    return __uint_as_float(u);
}

__device__ __forceinline__ void mma_tf32(float c[4],
                                         uint32_t a0, uint32_t a1, uint32_t a2, uint32_t a3,
                                         uint32_t b0, uint32_t b1) {
    asm volatile(
        "mma.sync.aligned.m16n8k8.row.col.f32.tf32.tf32.f32 "
        "{%0,%1,%2,%3}, {%4,%5,%6,%7}, {%8,%9}, {%0,%1,%2,%3};\n"
        : "+f"(c[0]), "+f"(c[1]), "+f"(c[2]), "+f"(c[3])
        : "r"(a0), "r"(a1), "r"(a2), "r"(a3), "r"(b0), "r"(b1));
}

__device__ __forceinline__ void mma_f16(float c[4],
                                        uint32_t a0, uint32_t a1, uint32_t a2, uint32_t a3,
                                        uint32_t b0, uint32_t b1) {
    asm volatile(
        "mma.sync.aligned.m16n8k16.row.col.f32.f16.f16.f32 "
        "{%0,%1,%2,%3}, {%4,%5,%6,%7}, {%8,%9}, {%0,%1,%2,%3};\n"
        : "+f"(c[0]), "+f"(c[1]), "+f"(c[2]), "+f"(c[3])
        : "r"(a0), "r"(a1), "r"(a2), "r"(a3), "r"(b0), "r"(b1));
}

__device__ __forceinline__ void ldm_x4(uint32_t& d0, uint32_t& d1, uint32_t& d2, uint32_t& d3,
                                       uint32_t addr) {
    asm volatile("ldmatrix.sync.aligned.m8n8.x4.shared.b16 {%0,%1,%2,%3}, [%4];"
                 : "=r"(d0), "=r"(d1), "=r"(d2), "=r"(d3) : "r"(addr));
}

__device__ __forceinline__ void cp16(uint32_t smem_addr, const void* gptr) {
    asm volatile("cp.async.cg.shared.global [%0], [%1], 16;\n"
                 :: "r"(smem_addr), "l"(gptr));
}

// ---------------------------------------------------------------------------
// Prepass: f32 -> f16 conversion (float4 in, 8 halfs out per slot)
// ---------------------------------------------------------------------------
__global__ void cvt_h_kernel(const float* __restrict__ src, __half* __restrict__ dst, int n8)
{
    int i = blockIdx.x * blockDim.x + threadIdx.x;
    if (i < n8) {
        float4 v0 = reinterpret_cast<const float4*>(src)[2 * i];
        float4 v1 = reinterpret_cast<const float4*>(src)[2 * i + 1];
        __half2 h[4];
        h[0] = __floats2half2_rn(v0.x, v0.y);
        h[1] = __floats2half2_rn(v0.z, v0.w);
        h[2] = __floats2half2_rn(v1.x, v1.y);
        h[3] = __floats2half2_rn(v1.z, v1.w);
        reinterpret_cast<uint4*>(dst)[i] = *reinterpret_cast<uint4*>(h);
    }
}

// ---------------------------------------------------------------------------
// fp16 GEMM:  C[m,n] = sum_k A[m,k]*B[n,k].  A,B fp16, fp32 accumulate.
// BM=128, BN=128, BK=64 halfs (128B/row data, 144B row stride), 3-stage
// cp.async, ldmatrix fragments, m16n8k16. 6 K-iterations.
// MODE 1: scatter to window-major f32 qkv. MODE 2: un-permute rows + bias.
// ---------------------------------------------------------------------------
#define ROW_B    144                       // bytes per smem row (stride)
#define TILE_B   (128 * ROW_B)             // 18432 per matrix
#define STAGE_B  (2 * TILE_B)              // 36864
#define SMEM_BYTES (3 * STAGE_B)           // 110592 -> 2 CTAs/SM

template<int MODE>
__global__ __launch_bounds__(256, 2) void gemm_f16_kernel(
    const __half* __restrict__ A, const __half* __restrict__ B,
    const float* __restrict__ bias, float* __restrict__ Cout, int N)
{
    extern __shared__ char smem[];

    const int tid  = threadIdx.x;
    const int lane = tid & 31;
    const int warp = tid >> 5;
    const int wm   = warp & 3;          // 0..3 along M
    const int wn   = warp >> 2;         // 0..1 along N
    const int g    = lane >> 2;
    const int t4   = lane & 3;

    const long bm = (long)blockIdx.y * 128;
    const long bn = (long)blockIdx.x * 128;

    const int lrow = tid >> 1;          // 0..127
    const int lcp  = (tid & 1) * 4;     // chunk base (0 or 4), 16B chunks

    float acc[2][8][4];
    #pragma unroll
    for (int i = 0; i < 2; i++)
        #pragma unroll
        for (int j = 0; j < 8; j++)
            #pragma unroll
            for (int k = 0; k < 4; k++) acc[i][j][k] = 0.f;

    const __half* gA = A + (bm + lrow) * (long)K_DIM;
    const __half* gB = B + (bn + lrow) * (long)K_DIM;

    const uint32_t sbase = (uint32_t)__cvta_generic_to_shared(smem);

    auto issue = [&](int stg, int kb) {   // kb in halfs
        uint32_t dA = sbase + stg * STAGE_B;
        uint32_t dB = dA + TILE_B;
        #pragma unroll
        for (int c = 0; c < 4; c++) {
            uint32_t off = lrow * ROW_B + (lcp + c) * 16;
            cp16(dA + off, gA + kb + (lcp + c) * 8);
            cp16(dB + off, gB + kb + (lcp + c) * 8);
        }
        asm volatile("cp.async.commit_group;\n");
    };

    // ldmatrix per-lane offsets (bytes)
    const int mi = lane >> 3, ri = lane & 7;
    // A m-tile: mi0:(m+ri, kblk0) mi1:(m+8+ri, kblk0) mi2:(m+ri, kblk1) mi3:(m+8+ri, kblk1)
    const uint32_t aOff = (wm * 32 + ((mi & 1) << 3) + ri) * ROW_B + ((mi >> 1) << 4);
    // B n-pair p: mi0:(n+ri,k0) mi1:(n+ri,k1) mi2:(n+8+ri,k0) mi3:(n+8+ri,k1)
    uint32_t bOff[4];
    #pragma unroll
    for (int p = 0; p < 4; p++)
        bOff[p] = (wn * 64 + p * 16 + ((mi >> 1) << 3) + ri) * ROW_B + ((mi & 1) << 4);

    issue(0, 0);
    issue(1, 64);

    for (int k = 0; k < 6; k++) {
        if (k < 4) asm volatile("cp.async.wait_group 1;\n");
        else       asm volatile("cp.async.wait_group 0;\n");
        __syncthreads();

        if (k + 2 < 6) issue((k + 2) % 3, (k + 2) * 64);

        const uint32_t stA = sbase + (k % 3) * STAGE_B;
        const uint32_t stB = stA + TILE_B;

        // hoist A fragments for the whole BK=64 block (k16 steps kq=0..3)
        uint32_t a[4][2][4];
        #pragma unroll
        for (int kq = 0; kq < 4; kq++)
            #pragma unroll
            for (int mt = 0; mt < 2; mt++)
                ldm_x4(a[kq][mt][0], a[kq][mt][1], a[kq][mt][2], a[kq][mt][3],
                       stA + aOff + mt * (16 * ROW_B) + kq * 32);

        #pragma unroll
        for (int kq = 0; kq < 4; kq++) {
            uint32_t bf[8][2];
            #pragma unroll
            for (int p = 0; p < 4; p++) {
                uint32_t d0, d1, d2, d3;
                ldm_x4(d0, d1, d2, d3, stB + bOff[p] + kq * 32);
                bf[2 * p    ][0] = d0; bf[2 * p    ][1] = d1;
                bf[2 * p + 1][0] = d2; bf[2 * p + 1][1] = d3;
            }
            #pragma unroll
            for (int mt = 0; mt < 2; mt++)
                #pragma unroll
                for (int nt = 0; nt < 8; nt++)
                    mma_f16(acc[mt][nt], a[kq][mt][0], a[kq][mt][1],
                            a[kq][mt][2], a[kq][mt][3], bf[nt][0], bf[nt][1]);
        }
    }

    // ---- epilogue ----
    #pragma unroll
    for (int mt = 0; mt < 2; mt++) {
        #pragma unroll
        for (int half_i = 0; half_i < 2; half_i++) {
            long row = bm + wm * 32 + mt * 16 + g + half_i * 8;

            if (MODE == 1) {
                // token row -> (window, slot); store f32 to window-major qkv
                int t  = (int)row;
                int b  = t / 3136;
                int r2 = t - b * 3136;
                int rr = r2 / 56;
                int cc = r2 - rr * 56;
                int w  = b * 64 + (rr / 7) * 8 + (cc / 7);
                int s  = (rr % 7) * 7 + (cc % 7);
                #pragma unroll
                for (int nt = 0; nt < 8; nt++) {
                    int col = (int)bn + wn * 64 + nt * 8 + 2 * t4;
                    int qkv = col / 384;
                    int rem = col - qkv * 384;
                    int h   = rem >> 5;
                    int d   = rem & 31;
                    long off = (long)((w * 3 + qkv) * 12 + h) * 1568 + s * 32 + d;
                    *reinterpret_cast<float2*>(g_qkv + off) =
                        make_float2(acc[mt][nt][2 * half_i], acc[mt][nt][2 * half_i + 1]);
                }
            } else {
                // window-major row -> token row, +bias, f32 out
                int r = (int)row;
                int w = r / 49;
                int s = r - w * 49;
                int b  = w >> 6;
                int wh = (w >> 3) & 7;
                int ww = w & 7;
                long tok = (long)b * 3136 + (wh * 7 + s / 7) * 56 + ww * 7 + (s % 7);
                #pragma unroll
                for (int nt = 0; nt < 8; nt++) {
                    long col = bn + wn * 64 + nt * 8 + 2 * t4;
                    float2 bv = *reinterpret_cast<const float2*>(bias + col);
                    *reinterpret_cast<float2*>(Cout + tok * (long)N + col) =
                        make_float2(acc[mt][nt][2 * half_i] + bv.x,
                                    acc[mt][nt][2 * half_i + 1] + bv.y);
                }
            }
        }
    }
}

// ---------------------------------------------------------------------------
// Windowed attention: one CTA per (head, window). tf32 mma internally;
// reads window-major f32 qkv; writes fp16 window-major rows for gemm3.
// ---------------------------------------------------------------------------
__global__ __launch_bounds__(256) void attn_kernel()
{
    __shared__ float qs[64][36];
    __shared__ float ks[64][36];
    __shared__ float vT[32][68];
    __shared__ float ps[64][68];

    const int tid  = threadIdx.x;
    const int lane = tid & 31;
    const int warp = tid >> 5;
    const int g    = lane >> 2;
    const int t4   = lane & 3;

    const int h = blockIdx.x;
    const int w = blockIdx.y;
    const float scale = 0.17677669529663687f;   // 1/sqrt(32)

    const float* qb = g_qkv + (long)((w * 3 + 0) * 12 + h) * 1568;
    const float* kb = g_qkv + (long)((w * 3 + 1) * 12 + h) * 1568;
    const float* vb = g_qkv + (long)((w * 3 + 2) * 12 + h) * 1568;

    for (int i = tid; i < 32 * 16; i += 256) {
        int d = i >> 4, c = 49 + (i & 15);
        vT[d][c] = 0.f;
    }

    for (int idx = tid; idx < 392; idx += 256) {
        int s = idx >> 3, dd = (idx & 7) << 2;
        float4 q4 = *reinterpret_cast<const float4*>(qb + idx * 4);
        float4 k4 = *reinterpret_cast<const float4*>(kb + idx * 4);
        float4 v4 = *reinterpret_cast<const float4*>(vb + idx * 4);
        qs[s][dd    ] = tf32r(q4.x * scale);
        qs[s][dd + 1] = tf32r(q4.y * scale);
        qs[s][dd + 2] = tf32r(q4.z * scale);
        qs[s][dd + 3] = tf32r(q4.w * scale);
        ks[s][dd    ] = tf32r(k4.x);
        ks[s][dd + 1] = tf32r(k4.y);
        ks[s][dd + 2] = tf32r(k4.z);
        ks[s][dd + 3] = tf32r(k4.w);
        vT[dd    ][s] = tf32r(v4.x);
        vT[dd + 1][s] = tf32r(v4.y);
        vT[dd + 2][s] = tf32r(v4.z);
        vT[dd + 3][s] = tf32r(v4.w);
    }
    __syncthreads();

    {
        float acc[4][4];
        #pragma unroll
        for (int j = 0; j < 4; j++)
            #pragma unroll
            for (int k = 0; k < 4; k++) acc[j][k] = 0.f;

        const int m = (warp & 3) * 16;
        #pragma unroll
        for (int kk = 0; kk < 32; kk += 8) {
            uint32_t a0 = __float_as_uint(qs[m + g    ][kk + t4    ]);
            uint32_t a1 = __float_as_uint(qs[m + g + 8][kk + t4    ]);
            uint32_t a2 = __float_as_uint(qs[m + g    ][kk + t4 + 4]);
            uint32_t a3 = __float_as_uint(qs[m + g + 8][kk + t4 + 4]);
            #pragma unroll
            for (int nt = 0; nt < 4; nt++) {
                int n = (warp >> 2) * 32 + nt * 8;
                uint32_t b0 = __float_as_uint(ks[n + g][kk + t4    ]);
                uint32_t b1 = __float_as_uint(ks[n + g][kk + t4 + 4]);
                mma_tf32(acc[nt], a0, a1, a2, a3, b0, b1);
            }
        }
        #pragma unroll
        for (int nt = 0; nt < 4; nt++) {
            int row = (warp & 3) * 16 + g;
            int col = (warp >> 2) * 32 + nt * 8 + 2 * t4;
            *reinterpret_cast<float2*>(&ps[row][col])     = make_float2(acc[nt][0], acc[nt][1]);
            *reinterpret_cast<float2*>(&ps[row + 8][col]) = make_float2(acc[nt][2], acc[nt][3]);
        }
    }
    __syncthreads();

    for (int r = warp; r < 49; r += 8) {
        float s0 = ps[r][lane];
        float s1 = ps[r][lane + 32];
        bool  v1 = (lane + 32) < 49;
        float mx = fmaxf(s0, v1 ? s1 : -1e30f);
        #pragma unroll
        for (int o = 16; o; o >>= 1) mx = fmaxf(mx, __shfl_xor_sync(0xffffffffu, mx, o));
        float e0 = __expf(s0 - mx);
        float e1 = v1 ? __expf(s1 - mx) : 0.f;
        float sm = e0 + e1;
        #pragma unroll
        for (int o = 16; o; o >>= 1) sm += __shfl_xor_sync(0xffffffffu, sm, o);
        float inv = 1.f / sm;
        ps[r][lane]      = tf32r(e0 * inv);
        ps[r][lane + 32] = tf32r(e1 * inv);
    }
    __syncthreads();

    {
        float acc[2][4];
        #pragma unroll
        for (int j = 0; j < 2; j++)
            #pragma unroll
            for (int k = 0; k < 4; k++) acc[j][k] = 0.f;

        const int m = (warp & 3) * 16;
        #pragma unroll
        for (int kk = 0; kk < 64; kk += 8) {
            uint32_t a0 = __float_as_uint(ps[m + g    ][kk + t4    ]);
            uint32_t a1 = __float_as_uint(ps[m + g + 8][kk + t4    ]);
            uint32_t a2 = __float_as_uint(ps[m + g    ][kk + t4 + 4]);
            uint32_t a3 = __float_as_uint(ps[m + g + 8][kk + t4 + 4]);
            #pragma unroll
            for (int j = 0; j < 2; j++) {
                int n = (warp >> 2) * 16 + j * 8;
                uint32_t b0 = __float_as_uint(vT[n + g][kk + t4    ]);
                uint32_t b1 = __float_as_uint(vT[n + g][kk + t4 + 4]);
                mma_tf32(acc[j], a0, a1, a2, a3, b0, b1);
            }
        }
        #pragma unroll
        for (int j = 0; j < 2; j++) {
            int col = (warp >> 2) * 16 + j * 8 + 2 * t4;
            #pragma unroll
            for (int i = 0; i < 2; i++) {
                int r = m + g + i * 8;
                if (r < 49) {
                    long off = (long)(w * 49 + r) * C_DIM + h * 32 + col;
                    *reinterpret_cast<__half2*>(g_att + off) =
                        __floats2half2_rn(acc[j][0 + 2 * i], acc[j][1 + 2 * i]);
                }
            }
        }
    }
}

// ---------------------------------------------------------------------------
extern "C" void kernel_launch(void* const* d_in, const int* in_sizes, int n_in,
                              void* d_out, int out_size)
{
    const float* x      = (const float*)d_in[0];
    const float* w_qkv  = (const float*)d_in[1];
    const float* w_proj = (const float*)d_in[2];
    const float* b_proj = (const float*)d_in[3];
    float* out = (float*)d_out;

    __half *xh, *wqkvh, *wprojh, *atth;
    cudaGetSymbolAddress((void**)&xh,     g_xh);
    cudaGetSymbolAddress((void**)&wqkvh,  g_wqkvh);
    cudaGetSymbolAddress((void**)&wprojh, g_wprojh);
    cudaGetSymbolAddress((void**)&atth,   g_att);

    cudaFuncSetAttribute(gemm_f16_kernel<1>,
                         cudaFuncAttributeMaxDynamicSharedMemorySize, SMEM_BYTES);
    cudaFuncSetAttribute(gemm_f16_kernel<2>,
                         cudaFuncAttributeMaxDynamicSharedMemorySize, SMEM_BYTES);

    // 0) f32 -> f16 prepass
    cvt_h_kernel<<<(M_TOK * C_DIM / 8 + 255) / 256, 256>>>(x, xh, M_TOK * C_DIM / 8);
    cvt_h_kernel<<<(QKV_DIM * C_DIM / 8 + 255) / 256, 256>>>(w_qkv, wqkvh, QKV_DIM * C_DIM / 8);
    cvt_h_kernel<<<(C_DIM * C_DIM / 8 + 255) / 256, 256>>>(w_proj, wprojh, C_DIM * C_DIM / 8);

    // 1) QKV projection (fp16 mma) -> window-major f32 qkv
    gemm_f16_kernel<1><<<dim3(QKV_DIM / 128, M_TOK / 128), 256, SMEM_BYTES>>>(
        xh, wqkvh, nullptr, nullptr, QKV_DIM);

    // 2) Windowed attention (tf32 mma) -> fp16 window-major rows
    attn_kernel<<<dim3(12, 1024), 256>>>();

    // 3) Output projection (fp16 mma) + bias; rows un-permuted to token order
    gemm_f16_kernel<2><<<dim3(C_DIM / 128, M_TOK / 128), 256, SMEM_BYTES>>>(
        atth, wprojh, b_proj, out, C_DIM);
}

// round 11
// speedup vs baseline: 1.2185x; 1.0179x over previous
#include <cuda_runtime.h>
#include <cuda_fp16.h>
#include <cstdint>

// B=16, N=3136 (56x56), C=384, NH=12, hd=32, WS=7, nW=1024, S=49.
#define M_TOK   50176
#define C_DIM   384
#define QKV_DIM 1152
#define K_DIM   384

// Scratch (device globals: allocation-free)
static __device__ __half g_xh  [(size_t)M_TOK * C_DIM];      // fp16 x
static __device__ __half g_wqkvh[QKV_DIM * C_DIM];           // fp16 weights
static __device__ __half g_wprojh[C_DIM * C_DIM];
// window-major qkv (f32): ((w*3+qkv)*12+h)*1568 + s*32 + d
static __device__ float  g_qkv[(size_t)M_TOK * QKV_DIM];
// window-major attn out (fp16): row = w*49+s, 384 cols
static __device__ __half g_att[(size_t)M_TOK * C_DIM];

__device__ __forceinline__ float tf32r(float x) {
    uint32_t u;
    asm("cvt.rna.tf32.f32 %0, %1;" : "=r"(u) : "f"(x));
    return __uint_as_float(u);
}

__device__ __forceinline__ void mma_tf32(float c[4],
                                         uint32_t a0, uint32_t a1, uint32_t a2, uint32_t a3,
                                         uint32_t b0, uint32_t b1) {
    asm volatile(
        "mma.sync.aligned.m16n8k8.row.col.f32.tf32.tf32.f32 "
        "{%0,%1,%2,%3}, {%4,%5,%6,%7}, {%8,%9}, {%0,%1,%2,%3};\n"
        : "+f"(c[0]), "+f"(c[1]), "+f"(c[2]), "+f"(c[3])
        : "r"(a0), "r"(a1), "r"(a2), "r"(a3), "r"(b0), "r"(b1));
}

__device__ __forceinline__ void mma_f16(float c[4],
                                        uint32_t a0, uint32_t a1, uint32_t a2, uint32_t a3,
                                        uint32_t b0, uint32_t b1) {
    asm volatile(
        "mma.sync.aligned.m16n8k16.row.col.f32.f16.f16.f32 "
        "{%0,%1,%2,%3}, {%4,%5,%6,%7}, {%8,%9}, {%0,%1,%2,%3};\n"
        : "+f"(c[0]), "+f"(c[1]), "+f"(c[2]), "+f"(c[3])
        : "r"(a0), "r"(a1), "r"(a2), "r"(a3), "r"(b0), "r"(b1));
}

__device__ __forceinline__ void ldm_x4(uint32_t& d0, uint32_t& d1, uint32_t& d2, uint32_t& d3,
                                       uint32_t addr) {
    asm volatile("ldmatrix.sync.aligned.m8n8.x4.shared.b16 {%0,%1,%2,%3}, [%4];"
                 : "=r"(d0), "=r"(d1), "=r"(d2), "=r"(d3) : "r"(addr));
}

__device__ __forceinline__ void cp16(uint32_t smem_addr, const void* gptr) {
    asm volatile("cp.async.cg.shared.global [%0], [%1], 16;\n"
                 :: "r"(smem_addr), "l"(gptr));
}

// ---------------------------------------------------------------------------
// Prepass: f32 -> f16 conversion
// ---------------------------------------------------------------------------
__global__ void cvt_h_kernel(const float* __restrict__ src, __half* __restrict__ dst, int n8)
{
    int i = blockIdx.x * blockDim.x + threadIdx.x;
    if (i < n8) {
        float4 v0 = reinterpret_cast<const float4*>(src)[2 * i];
        float4 v1 = reinterpret_cast<const float4*>(src)[2 * i + 1];
        __half2 h[4];
        h[0] = __floats2half2_rn(v0.x, v0.y);
        h[1] = __floats2half2_rn(v0.z, v0.w);
        h[2] = __floats2half2_rn(v1.x, v1.y);
        h[3] = __floats2half2_rn(v1.z, v1.w);
        reinterpret_cast<uint4*>(dst)[i] = *reinterpret_cast<uint4*>(h);
    }
}

// ---------------------------------------------------------------------------
// fp16 GEMM, software-pipelined fragments:  C[m,n] = sum_k A[m,k]*B[n,k].
// BM=128, BN=128, BK=64 halfs, 3-stage cp.async, ldmatrix ring buffers
// (A ring-2, B ring-2) so every ldmatrix is covered by 16 MMAs of work.
// MODE 1: scatter to window-major f32 qkv. MODE 2: un-permute rows + bias.
// ---------------------------------------------------------------------------
#define ROW_B    144
#define TILE_B   (128 * ROW_B)
#define STAGE_B  (2 * TILE_B)
#define SMEM_BYTES (3 * STAGE_B)           // 110592 -> 2 CTAs/SM

template<int MODE>
__global__ __launch_bounds__(256, 2) void gemm_f16_kernel(
    const __half* __restrict__ A, const __half* __restrict__ B,
    const float* __restrict__ bias, float* __restrict__ Cout, int N)
{
    extern __shared__ char smem[];

    const int tid  = threadIdx.x;
    const int lane = tid & 31;
    const int warp = tid >> 5;
    const int wm   = warp & 3;
    const int wn   = warp >> 2;
    const int g    = lane >> 2;
    const int t4   = lane & 3;

    const long bm = (long)blockIdx.y * 128;
    const long bn = (long)blockIdx.x * 128;

    const int lrow = tid >> 1;
    const int lcp  = (tid & 1) * 4;

    float acc[2][8][4];
    #pragma unroll
    for (int i = 0; i < 2; i++)
        #pragma unroll
        for (int j = 0; j < 8; j++)
            #pragma unroll
            for (int k = 0; k < 4; k++) acc[i][j][k] = 0.f;

    const __half* gA = A + (bm + lrow) * (long)K_DIM;
    const __half* gB = B + (bn + lrow) * (long)K_DIM;

    const uint32_t sbase = (uint32_t)__cvta_generic_to_shared(smem);

    auto issue = [&](int stg, int kb) {
        uint32_t dA = sbase + stg * STAGE_B;
        uint32_t dB = dA + TILE_B;
        #pragma unroll
        for (int c = 0; c < 4; c++) {
            uint32_t off = lrow * ROW_B + (lcp + c) * 16;
            cp16(dA + off, gA + kb + (lcp + c) * 8);
            cp16(dB + off, gB + kb + (lcp + c) * 8);
        }
        asm volatile("cp.async.commit_group;\n");
    };

    const int mi = lane >> 3, ri = lane & 7;
    const uint32_t aOff = (wm * 32 + ((mi & 1) << 3) + ri) * ROW_B + ((mi >> 1) << 4);
    uint32_t bOff[4];
    #pragma unroll
    for (int p = 0; p < 4; p++)
        bOff[p] = (wn * 64 + p * 16 + ((mi >> 1) << 3) + ri) * ROW_B + ((mi & 1) << 4);

    issue(0, 0);
    issue(1, 64);

    for (int k = 0; k < 6; k++) {
        if (k < 4) asm volatile("cp.async.wait_group 1;\n");
        else       asm volatile("cp.async.wait_group 0;\n");
        __syncthreads();

        if (k + 2 < 6) issue((k + 2) % 3, (k + 2) * 64);

        const uint32_t stA = sbase + (k % 3) * STAGE_B;
        const uint32_t stB = stA + TILE_B;

        uint32_t aR[2][2][4];     // [ring][mt][4]
        uint32_t bR[2][8][2];     // [ring][nt][2]

        auto ldA = [&](int kq, int r) {
            #pragma unroll
            for (int mt = 0; mt < 2; mt++)
                ldm_x4(aR[r][mt][0], aR[r][mt][1], aR[r][mt][2], aR[r][mt][3],
                       stA + aOff + mt * (16 * ROW_B) + kq * 32);
        };
        auto ldB = [&](int kq, int r) {
            #pragma unroll
            for (int p = 0; p < 4; p++) {
                uint32_t d0, d1, d2, d3;
                ldm_x4(d0, d1, d2, d3, stB + bOff[p] + kq * 32);
                bR[r][2 * p    ][0] = d0; bR[r][2 * p    ][1] = d1;
                bR[r][2 * p + 1][0] = d2; bR[r][2 * p + 1][1] = d3;
            }
        };

        // prologue of the per-stage pipeline
        ldA(0, 0);
        ldB(0, 0);
        ldA(1, 1);

        #pragma unroll
        for (int kq = 0; kq < 4; kq++) {
            const int cur = kq & 1;
            if (kq < 3) ldB(kq + 1, cur ^ 1);    // prefetch next B frags
            #pragma unroll
            for (int mt = 0; mt < 2; mt++)
                #pragma unroll
                for (int nt = 0; nt < 8; nt++)
                    mma_f16(acc[mt][nt], aR[cur][mt][0], aR[cur][mt][1],
                            aR[cur][mt][2], aR[cur][mt][3],
                            bR[cur][nt][0], bR[cur][nt][1]);
            if (kq < 2) ldA(kq + 2, cur);        // refill A ring behind MMAs
        }
    }

    // ---- epilogue ----
    #pragma unroll
    for (int mt = 0; mt < 2; mt++) {
        #pragma unroll
        for (int half_i = 0; half_i < 2; half_i++) {
            long row = bm + wm * 32 + mt * 16 + g + half_i * 8;

            if (MODE == 1) {
                int t  = (int)row;
                int b  = t / 3136;
                int r2 = t - b * 3136;
                int rr = r2 / 56;
                int cc = r2 - rr * 56;
                int w  = b * 64 + (rr / 7) * 8 + (cc / 7);
                int s  = (rr % 7) * 7 + (cc % 7);
                #pragma unroll
                for (int nt = 0; nt < 8; nt++) {
                    int col = (int)bn + wn * 64 + nt * 8 + 2 * t4;
                    int qkv = col / 384;
                    int rem = col - qkv * 384;
                    int h   = rem >> 5;
                    int d   = rem & 31;
                    long off = (long)((w * 3 + qkv) * 12 + h) * 1568 + s * 32 + d;
                    *reinterpret_cast<float2*>(g_qkv + off) =
                        make_float2(acc[mt][nt][2 * half_i], acc[mt][nt][2 * half_i + 1]);
                }
            } else {
                int r = (int)row;
                int w = r / 49;
                int s = r - w * 49;
                int b  = w >> 6;
                int wh = (w >> 3) & 7;
                int ww = w & 7;
                long tok = (long)b * 3136 + (wh * 7 + s / 7) * 56 + ww * 7 + (s % 7);
                #pragma unroll
                for (int nt = 0; nt < 8; nt++) {
                    long col = bn + wn * 64 + nt * 8 + 2 * t4;
                    float2 bv = *reinterpret_cast<const float2*>(bias + col);
                    *reinterpret_cast<float2*>(Cout + tok * (long)N + col) =
                        make_float2(acc[mt][nt][2 * half_i] + bv.x,
                                    acc[mt][nt][2 * half_i + 1] + bv.y);
                }
            }
        }
    }
}

// ---------------------------------------------------------------------------
// Windowed attention (unchanged from R10): one CTA per (head, window).
// ---------------------------------------------------------------------------
__global__ __launch_bounds__(256) void attn_kernel()
{
    __shared__ float qs[64][36];
    __shared__ float ks[64][36];
    __shared__ float vT[32][68];
    __shared__ float ps[64][68];

    const int tid  = threadIdx.x;
    const int lane = tid & 31;
    const int warp = tid >> 5;
    const int g    = lane >> 2;
    const int t4   = lane & 3;

    const int h = blockIdx.x;
    const int w = blockIdx.y;
    const float scale = 0.17677669529663687f;   // 1/sqrt(32)

    const float* qb = g_qkv + (long)((w * 3 + 0) * 12 + h) * 1568;
    const float* kb = g_qkv + (long)((w * 3 + 1) * 12 + h) * 1568;
    const float* vb = g_qkv + (long)((w * 3 + 2) * 12 + h) * 1568;

    for (int i = tid; i < 32 * 16; i += 256) {
        int d = i >> 4, c = 49 + (i & 15);
        vT[d][c] = 0.f;
    }

    for (int idx = tid; idx < 392; idx += 256) {
        int s = idx >> 3, dd = (idx & 7) << 2;
        float4 q4 = *reinterpret_cast<const float4*>(qb + idx * 4);
        float4 k4 = *reinterpret_cast<const float4*>(kb + idx * 4);
        float4 v4 = *reinterpret_cast<const float4*>(vb + idx * 4);
        qs[s][dd    ] = tf32r(q4.x * scale);
        qs[s][dd + 1] = tf32r(q4.y * scale);
        qs[s][dd + 2] = tf32r(q4.z * scale);
        qs[s][dd + 3] = tf32r(q4.w * scale);
        ks[s][dd    ] = tf32r(k4.x);
        ks[s][dd + 1] = tf32r(k4.y);
        ks[s][dd + 2] = tf32r(k4.z);
        ks[s][dd + 3] = tf32r(k4.w);
        vT[dd    ][s] = tf32r(v4.x);
        vT[dd + 1][s] = tf32r(v4.y);
        vT[dd + 2][s] = tf32r(v4.z);
        vT[dd + 3][s] = tf32r(v4.w);
    }
    __syncthreads();

    {
        float acc[4][4];
        #pragma unroll
        for (int j = 0; j < 4; j++)
            #pragma unroll
            for (int k = 0; k < 4; k++) acc[j][k] = 0.f;

        const int m = (warp & 3) * 16;
        #pragma unroll
        for (int kk = 0; kk < 32; kk += 8) {
            uint32_t a0 = __float_as_uint(qs[m + g    ][kk + t4    ]);
            uint32_t a1 = __float_as_uint(qs[m + g + 8][kk + t4    ]);
            uint32_t a2 = __float_as_uint(qs[m + g    ][kk + t4 + 4]);
            uint32_t a3 = __float_as_uint(qs[m + g + 8][kk + t4 + 4]);
            #pragma unroll
            for (int nt = 0; nt < 4; nt++) {
                int n = (warp >> 2) * 32 + nt * 8;
                uint32_t b0 = __float_as_uint(ks[n + g][kk + t4    ]);
                uint32_t b1 = __float_as_uint(ks[n + g][kk + t4 + 4]);
                mma_tf32(acc[nt], a0, a1, a2, a3, b0, b1);
            }
        }
        #pragma unroll
        for (int nt = 0; nt < 4; nt++) {
            int row = (warp & 3) * 16 + g;
            int col = (warp >> 2) * 32 + nt * 8 + 2 * t4;
            *reinterpret_cast<float2*>(&ps[row][col])     = make_float2(acc[nt][0], acc[nt][1]);
            *reinterpret_cast<float2*>(&ps[row + 8][col]) = make_float2(acc[nt][2], acc[nt][3]);
        }
    }
    __syncthreads();

    for (int r = warp; r < 49; r += 8) {
        float s0 = ps[r][lane];
        float s1 = ps[r][lane + 32];
        bool  v1 = (lane + 32) < 49;
        float mx = fmaxf(s0, v1 ? s1 : -1e30f);
        #pragma unroll
        for (int o = 16; o; o >>= 1) mx = fmaxf(mx, __shfl_xor_sync(0xffffffffu, mx, o));
        float e0 = __expf(s0 - mx);
        float e1 = v1 ? __expf(s1 - mx) : 0.f;
        float sm = e0 + e1;
        #pragma unroll
        for (int o = 16; o; o >>= 1) sm += __shfl_xor_sync(0xffffffffu, sm, o);
        float inv = 1.f / sm;
        ps[r][lane]      = tf32r(e0 * inv);
        ps[r][lane + 32] = tf32r(e1 * inv);
    }
    __syncthreads();

    {
        float acc[2][4];
        #pragma unroll
        for (int j = 0; j < 2; j++)
            #pragma unroll
            for (int k = 0; k < 4; k++) acc[j][k] = 0.f;

        const int m = (warp & 3) * 16;
        #pragma unroll
        for (int kk = 0; kk < 64; kk += 8) {
            uint32_t a0 = __float_as_uint(ps[m + g    ][kk + t4    ]);
            uint32_t a1 = __float_as_uint(ps[m + g + 8][kk + t4    ]);
            uint32_t a2 = __float_as_uint(ps[m + g    ][kk + t4 + 4]);
            uint32_t a3 = __float_as_uint(ps[m + g + 8][kk + t4 + 4]);
            #pragma unroll
            for (int j = 0; j < 2; j++) {
                int n = (warp >> 2) * 16 + j * 8;
                uint32_t b0 = __float_as_uint(vT[n + g][kk + t4    ]);
                uint32_t b1 = __float_as_uint(vT[n + g][kk + t4 + 4]);
                mma_tf32(acc[j], a0, a1, a2, a3, b0, b1);
            }
        }
        #pragma unroll
        for (int j = 0; j < 2; j++) {
            int col = (warp >> 2) * 16 + j * 8 + 2 * t4;
            #pragma unroll
            for (int i = 0; i < 2; i++) {
                int r = m + g + i * 8;
                if (r < 49) {
                    long off = (long)(w * 49 + r) * C_DIM + h * 32 + col;
                    *reinterpret_cast<__half2*>(g_att + off) =
                        __floats2half2_rn(acc[j][0 + 2 * i], acc[j][1 + 2 * i]);
                }
            }
        }
    }
}

// ---------------------------------------------------------------------------
extern "C" void kernel_launch(void* const* d_in, const int* in_sizes, int n_in,
                              void* d_out, int out_size)
{
    const float* x      = (const float*)d_in[0];
    const float* w_qkv  = (const float*)d_in[1];
    const float* w_proj = (const float*)d_in[2];
    const float* b_proj = (const float*)d_in[3];
    float* out = (float*)d_out;

    __half *xh, *wqkvh, *wprojh, *atth;
    cudaGetSymbolAddress((void**)&xh,     g_xh);
    cudaGetSymbolAddress((void**)&wqkvh,  g_wqkvh);
    cudaGetSymbolAddress((void**)&wprojh, g_wprojh);
    cudaGetSymbolAddress((void**)&atth,   g_att);

    cudaFuncSetAttribute(gemm_f16_kernel<1>,
                         cudaFuncAttributeMaxDynamicSharedMemorySize, SMEM_BYTES);
    cudaFuncSetAttribute(gemm_f16_kernel<2>,
                         cudaFuncAttributeMaxDynamicSharedMemorySize, SMEM_BYTES);

    // 0) f32 -> f16 prepass
    cvt_h_kernel<<<(M_TOK * C_DIM / 8 + 255) / 256, 256>>>(x, xh, M_TOK * C_DIM / 8);
    cvt_h_kernel<<<(QKV_DIM * C_DIM / 8 + 255) / 256, 256>>>(w_qkv, wqkvh, QKV_DIM * C_DIM / 8);
    cvt_h_kernel<<<(C_DIM * C_DIM / 8 + 255) / 256, 256>>>(w_proj, wprojh, C_DIM * C_DIM / 8);

    // 1) QKV projection (fp16 mma) -> window-major f32 qkv
    gemm_f16_kernel<1><<<dim3(QKV_DIM / 128, M_TOK / 128), 256, SMEM_BYTES>>>(
        xh, wqkvh, nullptr, nullptr, QKV_DIM);

    // 2) Windowed attention (tf32 mma) -> fp16 window-major rows
    attn_kernel<<<dim3(12, 1024), 256>>>();

    // 3) Output projection (fp16 mma) + bias; rows un-permuted to token order
    gemm_f16_kernel<2><<<dim3(C_DIM / 128, M_TOK / 128), 256, SMEM_BYTES>>>(
        atth, wprojh, b_proj, out, C_DIM);
}

// round 12
// speedup vs baseline: 1.4035x; 1.1518x over previous
#include <cuda_runtime.h>
#include <cuda_fp16.h>
#include <cstdint>

// B=16, N=3136 (56x56), C=384, NH=12, hd=32, WS=7, nW=1024, S=49.
#define M_TOK   50176
#define C_DIM   384
#define QKV_DIM 1152
#define K_DIM   384

// Scratch (device globals: allocation-free)
static __device__ __half g_xh  [(size_t)M_TOK * C_DIM];
static __device__ __half g_wqkvh[QKV_DIM * C_DIM];
static __device__ __half g_wprojh[C_DIM * C_DIM];
// window-major qkv (f32): ((w*3+qkv)*12+h)*1568 + s*32 + d
static __device__ float  g_qkv[(size_t)M_TOK * QKV_DIM];
// window-major attn out (fp16): row = w*49+s, 384 cols
static __device__ __half g_att[(size_t)M_TOK * C_DIM];

__device__ __forceinline__ float tf32r(float x) {
    uint32_t u;
    asm("cvt.rna.tf32.f32 %0, %1;" : "=r"(u) : "f"(x));
    return __uint_as_float(u);
}

__device__ __forceinline__ void mma_tf32(float c[4],
                                         uint32_t a0, uint32_t a1, uint32_t a2, uint32_t a3,
                                         uint32_t b0, uint32_t b1) {
    asm volatile(
        "mma.sync.aligned.m16n8k8.row.col.f32.tf32.tf32.f32 "
        "{%0,%1,%2,%3}, {%4,%5,%6,%7}, {%8,%9}, {%0,%1,%2,%3};\n"
        : "+f"(c[0]), "+f"(c[1]), "+f"(c[2]), "+f"(c[3])
        : "r"(a0), "r"(a1), "r"(a2), "r"(a3), "r"(b0), "r"(b1));
}

__device__ __forceinline__ void mma_f16(float c[4],
                                        uint32_t a0, uint32_t a1, uint32_t a2, uint32_t a3,
                                        uint32_t b0, uint32_t b1) {
    asm volatile(
        "mma.sync.aligned.m16n8k16.row.col.f32.f16.f16.f32 "
        "{%0,%1,%2,%3}, {%4,%5,%6,%7}, {%8,%9}, {%0,%1,%2,%3};\n"
        : "+f"(c[0]), "+f"(c[1]), "+f"(c[2]), "+f"(c[3])
        : "r"(a0), "r"(a1), "r"(a2), "r"(a3), "r"(b0), "r"(b1));
}

__device__ __forceinline__ void ldm_x4(uint32_t& d0, uint32_t& d1, uint32_t& d2, uint32_t& d3,
                                       uint32_t addr) {
    asm volatile("ldmatrix.sync.aligned.m8n8.x4.shared.b16 {%0,%1,%2,%3}, [%4];"
                 : "=r"(d0), "=r"(d1), "=r"(d2), "=r"(d3) : "r"(addr));
}

__device__ __forceinline__ void cp16(uint32_t smem_addr, const void* gptr) {
    asm volatile("cp.async.cg.shared.global [%0], [%1], 16;\n"
                 :: "r"(smem_addr), "l"(gptr));
}

// ---------------------------------------------------------------------------
// Prepass: f32 -> f16 conversion
// ---------------------------------------------------------------------------
__global__ void cvt_h_kernel(const float* __restrict__ src, __half* __restrict__ dst, int n8)
{
    int i = blockIdx.x * blockDim.x + threadIdx.x;
    if (i < n8) {
        float4 v0 = reinterpret_cast<const float4*>(src)[2 * i];
        float4 v1 = reinterpret_cast<const float4*>(src)[2 * i + 1];
        __half2 h[4];
        h[0] = __floats2half2_rn(v0.x, v0.y);
        h[1] = __floats2half2_rn(v0.z, v0.w);
        h[2] = __floats2half2_rn(v1.x, v1.y);
        h[3] = __floats2half2_rn(v1.z, v1.w);
        reinterpret_cast<uint4*>(dst)[i] = *reinterpret_cast<uint4*>(h);
    }
}

// ---------------------------------------------------------------------------
// fp16 GEMM, 512 threads (16 warps = 4x4), warp tile 32x32.
// BM=128, BN=128, BK=64 halfs, 3-stage cp.async, ldmatrix fragments.
// 2 CTAs/SM -> 32 warps/SM = 4 warps/SMSP for latency hiding.
// MODE 1: scatter to window-major f32 qkv. MODE 2: un-permute rows + bias.
// ---------------------------------------------------------------------------
#define ROW_B    144
#define TILE_B   (128 * ROW_B)
#define STAGE_B  (2 * TILE_B)
#define SMEM_BYTES (3 * STAGE_B)           // 110592 -> 2 CTAs/SM

template<int MODE>
__global__ __launch_bounds__(512, 2) void gemm_f16_kernel(
    const __half* __restrict__ A, const __half* __restrict__ B,
    const float* __restrict__ bias, float* __restrict__ Cout, int N)
{
    extern __shared__ char smem[];

    const int tid  = threadIdx.x;
    const int lane = tid & 31;
    const int warp = tid >> 5;
    const int wm   = warp & 3;          // 0..3 along M (32 rows)
    const int wn   = warp >> 2;         // 0..3 along N (32 cols)
    const int g    = lane >> 2;
    const int t4   = lane & 3;

    const long bm = (long)blockIdx.y * 128;
    const long bn = (long)blockIdx.x * 128;

    const int lrow = tid >> 2;          // 0..127
    const int lcp  = (tid & 3) * 2;     // chunk base (0,2,4,6), 16B chunks

    float acc[2][4][4];
    #pragma unroll
    for (int i = 0; i < 2; i++)
        #pragma unroll
        for (int j = 0; j < 4; j++)
            #pragma unroll
            for (int k = 0; k < 4; k++) acc[i][j][k] = 0.f;

    const __half* gA = A + (bm + lrow) * (long)K_DIM;
    const __half* gB = B + (bn + lrow) * (long)K_DIM;

    const uint32_t sbase = (uint32_t)__cvta_generic_to_shared(smem);

    auto issue = [&](int stg, int kb) {   // kb in halfs
        uint32_t dA = sbase + stg * STAGE_B;
        uint32_t dB = dA + TILE_B;
        #pragma unroll
        for (int c = 0; c < 2; c++) {
            uint32_t off = lrow * ROW_B + (lcp + c) * 16;
            cp16(dA + off, gA + kb + (lcp + c) * 8);
            cp16(dB + off, gB + kb + (lcp + c) * 8);
        }
        asm volatile("cp.async.commit_group;\n");
    };

    // ldmatrix per-lane offsets (bytes)
    const int mi = lane >> 3, ri = lane & 7;
    const uint32_t aOff = (wm * 32 + ((mi & 1) << 3) + ri) * ROW_B + ((mi >> 1) << 4);
    uint32_t bOff[2];
    #pragma unroll
    for (int p = 0; p < 2; p++)
        bOff[p] = (wn * 32 + p * 16 + ((mi >> 1) << 3) + ri) * ROW_B + ((mi & 1) << 4);

    issue(0, 0);
    issue(1, 64);

    for (int k = 0; k < 6; k++) {
        if (k < 4) asm volatile("cp.async.wait_group 1;\n");
        else       asm volatile("cp.async.wait_group 0;\n");
        __syncthreads();

        if (k + 2 < 6) issue((k + 2) % 3, (k + 2) * 64);

        const uint32_t stA = sbase + (k % 3) * STAGE_B;
        const uint32_t stB = stA + TILE_B;

        #pragma unroll
        for (int kq = 0; kq < 4; kq++) {
            uint32_t a[2][4];
            #pragma unroll
            for (int mt = 0; mt < 2; mt++)
                ldm_x4(a[mt][0], a[mt][1], a[mt][2], a[mt][3],
                       stA + aOff + mt * (16 * ROW_B) + kq * 32);

            uint32_t bf[4][2];
            #pragma unroll
            for (int p = 0; p < 2; p++) {
                uint32_t d0, d1, d2, d3;
                ldm_x4(d0, d1, d2, d3, stB + bOff[p] + kq * 32);
                bf[2 * p    ][0] = d0; bf[2 * p    ][1] = d1;
                bf[2 * p + 1][0] = d2; bf[2 * p + 1][1] = d3;
            }

            #pragma unroll
            for (int mt = 0; mt < 2; mt++)
                #pragma unroll
                for (int nt = 0; nt < 4; nt++)
                    mma_f16(acc[mt][nt], a[mt][0], a[mt][1], a[mt][2], a[mt][3],
                            bf[nt][0], bf[nt][1]);
        }
    }

    // ---- epilogue ----
    #pragma unroll
    for (int mt = 0; mt < 2; mt++) {
        #pragma unroll
        for (int half_i = 0; half_i < 2; half_i++) {
            long row = bm + wm * 32 + mt * 16 + g + half_i * 8;

            if (MODE == 1) {
                int t  = (int)row;
                int b  = t / 3136;
                int r2 = t - b * 3136;
                int rr = r2 / 56;
                int cc = r2 - rr * 56;
                int w  = b * 64 + (rr / 7) * 8 + (cc / 7);
                int s  = (rr % 7) * 7 + (cc % 7);
                #pragma unroll
                for (int nt = 0; nt < 4; nt++) {
                    int col = (int)bn + wn * 32 + nt * 8 + 2 * t4;
                    int qkv = col / 384;
                    int rem = col - qkv * 384;
                    int h   = rem >> 5;
                    int d   = rem & 31;
                    long off = (long)((w * 3 + qkv) * 12 + h) * 1568 + s * 32 + d;
                    *reinterpret_cast<float2*>(g_qkv + off) =
                        make_float2(acc[mt][nt][2 * half_i], acc[mt][nt][2 * half_i + 1]);
                }
            } else {
                int r = (int)row;
                int w = r / 49;
                int s = r - w * 49;
                int b  = w >> 6;
                int wh = (w >> 3) & 7;
                int ww = w & 7;
                long tok = (long)b * 3136 + (wh * 7 + s / 7) * 56 + ww * 7 + (s % 7);
                #pragma unroll
                for (int nt = 0; nt < 4; nt++) {
                    long col = bn + wn * 32 + nt * 8 + 2 * t4;
                    float2 bv = *reinterpret_cast<const float2*>(bias + col);
                    *reinterpret_cast<float2*>(Cout + tok * (long)N + col) =
                        make_float2(acc[mt][nt][2 * half_i] + bv.x,
                                    acc[mt][nt][2 * half_i + 1] + bv.y);
                }
            }
        }
    }
}

// ---------------------------------------------------------------------------
// Windowed attention (unchanged): one CTA per (head, window).
// ---------------------------------------------------------------------------
__global__ __launch_bounds__(256) void attn_kernel()
{
    __shared__ float qs[64][36];
    __shared__ float ks[64][36];
    __shared__ float vT[32][68];
    __shared__ float ps[64][68];

    const int tid  = threadIdx.x;
    const int lane = tid & 31;
    const int warp = tid >> 5;
    const int g    = lane >> 2;
    const int t4   = lane & 3;

    const int h = blockIdx.x;
    const int w = blockIdx.y;
    const float scale = 0.17677669529663687f;   // 1/sqrt(32)

    const float* qb = g_qkv + (long)((w * 3 + 0) * 12 + h) * 1568;
    const float* kb = g_qkv + (long)((w * 3 + 1) * 12 + h) * 1568;
    const float* vb = g_qkv + (long)((w * 3 + 2) * 12 + h) * 1568;

    for (int i = tid; i < 32 * 16; i += 256) {
        int d = i >> 4, c = 49 + (i & 15);
        vT[d][c] = 0.f;
    }

    for (int idx = tid; idx < 392; idx += 256) {
        int s = idx >> 3, dd = (idx & 7) << 2;
        float4 q4 = *reinterpret_cast<const float4*>(qb + idx * 4);
        float4 k4 = *reinterpret_cast<const float4*>(kb + idx * 4);
        float4 v4 = *reinterpret_cast<const float4*>(vb + idx * 4);
        qs[s][dd    ] = tf32r(q4.x * scale);
        qs[s][dd + 1] = tf32r(q4.y * scale);
        qs[s][dd + 2] = tf32r(q4.z * scale);
        qs[s][dd + 3] = tf32r(q4.w * scale);
        ks[s][dd    ] = tf32r(k4.x);
        ks[s][dd + 1] = tf32r(k4.y);
        ks[s][dd + 2] = tf32r(k4.z);
        ks[s][dd + 3] = tf32r(k4.w);
        vT[dd    ][s] = tf32r(v4.x);
        vT[dd + 1][s] = tf32r(v4.y);
        vT[dd + 2][s] = tf32r(v4.z);
        vT[dd + 3][s] = tf32r(v4.w);
    }
    __syncthreads();

    {
        float acc[4][4];
        #pragma unroll
        for (int j = 0; j < 4; j++)
            #pragma unroll
            for (int k = 0; k < 4; k++) acc[j][k] = 0.f;

        const int m = (warp & 3) * 16;
        #pragma unroll
        for (int kk = 0; kk < 32; kk += 8) {
            uint32_t a0 = __float_as_uint(qs[m + g    ][kk + t4    ]);
            uint32_t a1 = __float_as_uint(qs[m + g + 8][kk + t4    ]);
            uint32_t a2 = __float_as_uint(qs[m + g    ][kk + t4 + 4]);
            uint32_t a3 = __float_as_uint(qs[m + g + 8][kk + t4 + 4]);
            #pragma unroll
            for (int nt = 0; nt < 4; nt++) {
                int n = (warp >> 2) * 32 + nt * 8;
                uint32_t b0 = __float_as_uint(ks[n + g][kk + t4    ]);
                uint32_t b1 = __float_as_uint(ks[n + g][kk + t4 + 4]);
                mma_tf32(acc[nt], a0, a1, a2, a3, b0, b1);
            }
        }
        #pragma unroll
        for (int nt = 0; nt < 4; nt++) {
            int row = (warp & 3) * 16 + g;
            int col = (warp >> 2) * 32 + nt * 8 + 2 * t4;
            *reinterpret_cast<float2*>(&ps[row][col])     = make_float2(acc[nt][0], acc[nt][1]);
            *reinterpret_cast<float2*>(&ps[row + 8][col]) = make_float2(acc[nt][2], acc[nt][3]);
        }
    }
    __syncthreads();

    for (int r = warp; r < 49; r += 8) {
        float s0 = ps[r][lane];
        float s1 = ps[r][lane + 32];
        bool  v1 = (lane + 32) < 49;
        float mx = fmaxf(s0, v1 ? s1 : -1e30f);
        #pragma unroll
        for (int o = 16; o; o >>= 1) mx = fmaxf(mx, __shfl_xor_sync(0xffffffffu, mx, o));
        float e0 = __expf(s0 - mx);
        float e1 = v1 ? __expf(s1 - mx) : 0.f;
        float sm = e0 + e1;
        #pragma unroll
        for (int o = 16; o; o >>= 1) sm += __shfl_xor_sync(0xffffffffu, sm, o);
        float inv = 1.f / sm;
        ps[r][lane]      = tf32r(e0 * inv);
        ps[r][lane + 32] = tf32r(e1 * inv);
    }
    __syncthreads();

    {
        float acc[2][4];
        #pragma unroll
        for (int j = 0; j < 2; j++)
            #pragma unroll
            for (int k = 0; k < 4; k++) acc[j][k] = 0.f;

        const int m = (warp & 3) * 16;
        #pragma unroll
        for (int kk = 0; kk < 64; kk += 8) {
            uint32_t a0 = __float_as_uint(ps[m + g    ][kk + t4    ]);
            uint32_t a1 = __float_as_uint(ps[m + g + 8][kk + t4    ]);
            uint32_t a2 = __float_as_uint(ps[m + g    ][kk + t4 + 4]);
            uint32_t a3 = __float_as_uint(ps[m + g + 8][kk + t4 + 4]);
            #pragma unroll
            for (int j = 0; j < 2; j++) {
                int n = (warp >> 2) * 16 + j * 8;
                uint32_t b0 = __float_as_uint(vT[n + g][kk + t4    ]);
                uint32_t b1 = __float_as_uint(vT[n + g][kk + t4 + 4]);
                mma_tf32(acc[j], a0, a1, a2, a3, b0, b1);
            }
        }
        #pragma unroll
        for (int j = 0; j < 2; j++) {
            int col = (warp >> 2) * 16 + j * 8 + 2 * t4;
            #pragma unroll
            for (int i = 0; i < 2; i++) {
                int r = m + g + i * 8;
                if (r < 49) {
                    long off = (long)(w * 49 + r) * C_DIM + h * 32 + col;
                    *reinterpret_cast<__half2*>(g_att + off) =
                        __floats2half2_rn(acc[j][0 + 2 * i], acc[j][1 + 2 * i]);
                }
            }
        }
    }
}

// ---------------------------------------------------------------------------
extern "C" void kernel_launch(void* const* d_in, const int* in_sizes, int n_in,
                              void* d_out, int out_size)
{
    const float* x      = (const float*)d_in[0];
    const float* w_qkv  = (const float*)d_in[1];
    const float* w_proj = (const float*)d_in[2];
    const float* b_proj = (const float*)d_in[3];
    float* out = (float*)d_out;

    __half *xh, *wqkvh, *wprojh, *atth;
    cudaGetSymbolAddress((void**)&xh,     g_xh);
    cudaGetSymbolAddress((void**)&wqkvh,  g_wqkvh);
    cudaGetSymbolAddress((void**)&wprojh, g_wprojh);
    cudaGetSymbolAddress((void**)&atth,   g_att);

    cudaFuncSetAttribute(gemm_f16_kernel<1>,
                         cudaFuncAttributeMaxDynamicSharedMemorySize, SMEM_BYTES);
    cudaFuncSetAttribute(gemm_f16_kernel<2>,
                         cudaFuncAttributeMaxDynamicSharedMemorySize, SMEM_BYTES);

    // 0) f32 -> f16 prepass
    cvt_h_kernel<<<(M_TOK * C_DIM / 8 + 255) / 256, 256>>>(x, xh, M_TOK * C_DIM / 8);
    cvt_h_kernel<<<(QKV_DIM * C_DIM / 8 + 255) / 256, 256>>>(w_qkv, wqkvh, QKV_DIM * C_DIM / 8);
    cvt_h_kernel<<<(C_DIM * C_DIM / 8 + 255) / 256, 256>>>(w_proj, wprojh, C_DIM * C_DIM / 8);

    // 1) QKV projection (fp16 mma, 512 thr) -> window-major f32 qkv
    gemm_f16_kernel<1><<<dim3(QKV_DIM / 128, M_TOK / 128), 512, SMEM_BYTES>>>(
        xh, wqkvh, nullptr, nullptr, QKV_DIM);

    // 2) Windowed attention (tf32 mma) -> fp16 window-major rows
    attn_kernel<<<dim3(12, 1024), 256>>>();

    // 3) Output projection (fp16 mma, 512 thr) + bias; rows -> token order
    gemm_f16_kernel<2><<<dim3(C_DIM / 128, M_TOK / 128), 512, SMEM_BYTES>>>(
        atth, wprojh, b_proj, out, C_DIM);
}

// round 13
// speedup vs baseline: 1.5275x; 1.0883x over previous
#include <cuda_runtime.h>
#include <cuda_fp16.h>
#include <cstdint>

// B=16, N=3136 (56x56), C=384, NH=12, hd=32, WS=7, nW=1024, S=49.
#define M_TOK   50176
#define C_DIM   384
#define QKV_DIM 1152
#define K_DIM   384

// Scratch (device globals: allocation-free)
static __device__ __half g_xh  [(size_t)M_TOK * C_DIM];
static __device__ __half g_wqkvh[QKV_DIM * C_DIM];
static __device__ __half g_wprojh[C_DIM * C_DIM];
// window-major qkv (fp16): ((w*3+qkv)*12+h)*1568 + s*32 + d
static __device__ __half g_qkvh[(size_t)M_TOK * QKV_DIM];
// window-major attn out (fp16): row = w*49+s, 384 cols
static __device__ __half g_att[(size_t)M_TOK * C_DIM];

__device__ __forceinline__ void mma_f16(float c[4],
                                        uint32_t a0, uint32_t a1, uint32_t a2, uint32_t a3,
                                        uint32_t b0, uint32_t b1) {
    asm volatile(
        "mma.sync.aligned.m16n8k16.row.col.f32.f16.f16.f32 "
        "{%0,%1,%2,%3}, {%4,%5,%6,%7}, {%8,%9}, {%0,%1,%2,%3};\n"
        : "+f"(c[0]), "+f"(c[1]), "+f"(c[2]), "+f"(c[3])
        : "r"(a0), "r"(a1), "r"(a2), "r"(a3), "r"(b0), "r"(b1));
}

__device__ __forceinline__ void ldm_x4(uint32_t& d0, uint32_t& d1, uint32_t& d2, uint32_t& d3,
                                       uint32_t addr) {
    asm volatile("ldmatrix.sync.aligned.m8n8.x4.shared.b16 {%0,%1,%2,%3}, [%4];"
                 : "=r"(d0), "=r"(d1), "=r"(d2), "=r"(d3) : "r"(addr));
}

__device__ __forceinline__ void cp16(uint32_t smem_addr, const void* gptr) {
    asm volatile("cp.async.cg.shared.global [%0], [%1], 16;\n"
                 :: "r"(smem_addr), "l"(gptr));
}

// ---------------------------------------------------------------------------
// Prepass: f32 -> f16 conversion
// ---------------------------------------------------------------------------
__global__ void cvt_h_kernel(const float* __restrict__ src, __half* __restrict__ dst, int n8)
{
    int i = blockIdx.x * blockDim.x + threadIdx.x;
    if (i < n8) {
        float4 v0 = reinterpret_cast<const float4*>(src)[2 * i];
        float4 v1 = reinterpret_cast<const float4*>(src)[2 * i + 1];
        __half2 h[4];
        h[0] = __floats2half2_rn(v0.x, v0.y);
        h[1] = __floats2half2_rn(v0.z, v0.w);
        h[2] = __floats2half2_rn(v1.x, v1.y);
        h[3] = __floats2half2_rn(v1.z, v1.w);
        reinterpret_cast<uint4*>(dst)[i] = *reinterpret_cast<uint4*>(h);
    }
}

// ---------------------------------------------------------------------------
// fp16 GEMM, 512 threads (16 warps = 4x4), warp tile 32x32.
// BM=128, BN=128, BK=64 halfs, 3-stage cp.async, ldmatrix fragments.
// MODE 1: scatter fp16 to window-major qkv. MODE 2: un-permute rows + bias.
// ---------------------------------------------------------------------------
#define ROW_B    144
#define TILE_B   (128 * ROW_B)
#define STAGE_B  (2 * TILE_B)
#define SMEM_BYTES (3 * STAGE_B)           // 110592 -> 2 CTAs/SM

template<int MODE>
__global__ __launch_bounds__(512, 2) void gemm_f16_kernel(
    const __half* __restrict__ A, const __half* __restrict__ B,
    const float* __restrict__ bias, float* __restrict__ Cout, int N)
{
    extern __shared__ char smem[];

    const int tid  = threadIdx.x;
    const int lane = tid & 31;
    const int warp = tid >> 5;
    const int wm   = warp & 3;          // 0..3 along M (32 rows)
    const int wn   = warp >> 2;         // 0..3 along N (32 cols)
    const int g    = lane >> 2;
    const int t4   = lane & 3;

    const long bm = (long)blockIdx.y * 128;
    const long bn = (long)blockIdx.x * 128;

    const int lrow = tid >> 2;          // 0..127
    const int lcp  = (tid & 3) * 2;     // chunk base (0,2,4,6), 16B chunks

    float acc[2][4][4];
    #pragma unroll
    for (int i = 0; i < 2; i++)
        #pragma unroll
        for (int j = 0; j < 4; j++)
            #pragma unroll
            for (int k = 0; k < 4; k++) acc[i][j][k] = 0.f;

    const __half* gA = A + (bm + lrow) * (long)K_DIM;
    const __half* gB = B + (bn + lrow) * (long)K_DIM;

    const uint32_t sbase = (uint32_t)__cvta_generic_to_shared(smem);

    auto issue = [&](int stg, int kb) {   // kb in halfs
        uint32_t dA = sbase + stg * STAGE_B;
        uint32_t dB = dA + TILE_B;
        #pragma unroll
        for (int c = 0; c < 2; c++) {
            uint32_t off = lrow * ROW_B + (lcp + c) * 16;
            cp16(dA + off, gA + kb + (lcp + c) * 8);
            cp16(dB + off, gB + kb + (lcp + c) * 8);
        }
        asm volatile("cp.async.commit_group;\n");
    };

    const int mi = lane >> 3, ri = lane & 7;
    const uint32_t aOff = (wm * 32 + ((mi & 1) << 3) + ri) * ROW_B + ((mi >> 1) << 4);
    uint32_t bOff[2];
    #pragma unroll
    for (int p = 0; p < 2; p++)
        bOff[p] = (wn * 32 + p * 16 + ((mi >> 1) << 3) + ri) * ROW_B + ((mi & 1) << 4);

    issue(0, 0);
    issue(1, 64);

    for (int k = 0; k < 6; k++) {
        if (k < 4) asm volatile("cp.async.wait_group 1;\n");
        else       asm volatile("cp.async.wait_group 0;\n");
        __syncthreads();

        if (k + 2 < 6) issue((k + 2) % 3, (k + 2) * 64);

        const uint32_t stA = sbase + (k % 3) * STAGE_B;
        const uint32_t stB = stA + TILE_B;

        #pragma unroll
        for (int kq = 0; kq < 4; kq++) {
            uint32_t a[2][4];
            #pragma unroll
            for (int mt = 0; mt < 2; mt++)
                ldm_x4(a[mt][0], a[mt][1], a[mt][2], a[mt][3],
                       stA + aOff + mt * (16 * ROW_B) + kq * 32);

            uint32_t bf[4][2];
            #pragma unroll
            for (int p = 0; p < 2; p++) {
                uint32_t d0, d1, d2, d3;
                ldm_x4(d0, d1, d2, d3, stB + bOff[p] + kq * 32);
                bf[2 * p    ][0] = d0; bf[2 * p    ][1] = d1;
                bf[2 * p + 1][0] = d2; bf[2 * p + 1][1] = d3;
            }

            #pragma unroll
            for (int mt = 0; mt < 2; mt++)
                #pragma unroll
                for (int nt = 0; nt < 4; nt++)
                    mma_f16(acc[mt][nt], a[mt][0], a[mt][1], a[mt][2], a[mt][3],
                            bf[nt][0], bf[nt][1]);
        }
    }

    // ---- epilogue ----
    #pragma unroll
    for (int mt = 0; mt < 2; mt++) {
        #pragma unroll
        for (int half_i = 0; half_i < 2; half_i++) {
            long row = bm + wm * 32 + mt * 16 + g + half_i * 8;

            if (MODE == 1) {
                int t  = (int)row;
                int b  = t / 3136;
                int r2 = t - b * 3136;
                int rr = r2 / 56;
                int cc = r2 - rr * 56;
                int w  = b * 64 + (rr / 7) * 8 + (cc / 7);
                int s  = (rr % 7) * 7 + (cc % 7);
                #pragma unroll
                for (int nt = 0; nt < 4; nt++) {
                    int col = (int)bn + wn * 32 + nt * 8 + 2 * t4;
                    int qkv = col / 384;
                    int rem = col - qkv * 384;
                    int h   = rem >> 5;
                    int d   = rem & 31;
                    long off = (long)((w * 3 + qkv) * 12 + h) * 1568 + s * 32 + d;
                    *reinterpret_cast<__half2*>(g_qkvh + off) =
                        __floats2half2_rn(acc[mt][nt][2 * half_i], acc[mt][nt][2 * half_i + 1]);
                }
            } else {
                int r = (int)row;
                int w = r / 49;
                int s = r - w * 49;
                int b  = w >> 6;
                int wh = (w >> 3) & 7;
                int ww = w & 7;
                long tok = (long)b * 3136 + (wh * 7 + s / 7) * 56 + ww * 7 + (s % 7);
                #pragma unroll
                for (int nt = 0; nt < 4; nt++) {
                    long col = bn + wn * 32 + nt * 8 + 2 * t4;
                    float2 bv = *reinterpret_cast<const float2*>(bias + col);
                    *reinterpret_cast<float2*>(Cout + tok * (long)N + col) =
                        make_float2(acc[mt][nt][2 * half_i] + bv.x,
                                    acc[mt][nt][2 * half_i + 1] + bv.y);
                }
            }
        }
    }
}

// ---------------------------------------------------------------------------
// Windowed attention, fp16 mma: one CTA per (head, window). S=49 pad 64.
// Q/K/V fp16 in smem (padded strides 40 / 72 halfs: conflict-free half2
// fragment loads). Softmax in f32 with scale applied to scores; P fp16.
// ---------------------------------------------------------------------------
__global__ __launch_bounds__(256) void attn_kernel()
{
    __shared__ __half qs[64][40];
    __shared__ __half ks[64][40];
    __shared__ __half vT[32][72];
    __shared__ float  sc[64][68];
    __shared__ __half ph[64][72];

    const int tid  = threadIdx.x;
    const int lane = tid & 31;
    const int warp = tid >> 5;
    const int g    = lane >> 2;
    const int t4   = lane & 3;

    const int h = blockIdx.x;
    const int w = blockIdx.y;
    const float scale = 0.17677669529663687f;   // 1/sqrt(32)

    const __half* qb = g_qkvh + (long)((w * 3 + 0) * 12 + h) * 1568;
    const __half* kb = g_qkvh + (long)((w * 3 + 1) * 12 + h) * 1568;
    const __half* vb = g_qkvh + (long)((w * 3 + 2) * 12 + h) * 1568;

    // zero vT pad cols 49..63 (other pad garbage is masked/discarded)
    for (int i = tid; i < 32 * 15; i += 256) {
        int d = i / 15, c = 49 + (i % 15);
        vT[d][c] = __ushort_as_half(0);
    }

    // coalesced uint4 loads: 196 slots of 8 halfs per matrix
    for (int idx = tid; idx < 196; idx += 256) {
        int s = idx >> 2, dd = (idx & 3) << 3;
        uint4 q4 = *reinterpret_cast<const uint4*>(qb + idx * 8);
        uint4 k4 = *reinterpret_cast<const uint4*>(kb + idx * 8);
        uint4 v4 = *reinterpret_cast<const uint4*>(vb + idx * 8);
        *reinterpret_cast<uint4*>(&qs[s][dd]) = q4;
        *reinterpret_cast<uint4*>(&ks[s][dd]) = k4;
        const __half* vh = reinterpret_cast<const __half*>(&v4);
        #pragma unroll
        for (int i = 0; i < 8; i++) vT[dd + i][s] = vh[i];
    }
    __syncthreads();

    // ---- scores = Q @ K^T  (64x64x32, fp16 mma, 2 k16 steps)
    {
        float acc[4][4];
        #pragma unroll
        for (int j = 0; j < 4; j++)
            #pragma unroll
            for (int k = 0; k < 4; k++) acc[j][k] = 0.f;

        const int m = (warp & 3) * 16;
        #pragma unroll
        for (int kq = 0; kq < 2; kq++) {
            int kc = kq * 16 + 2 * t4;
            uint32_t a0 = *reinterpret_cast<const uint32_t*>(&qs[m + g    ][kc    ]);
            uint32_t a1 = *reinterpret_cast<const uint32_t*>(&qs[m + g + 8][kc    ]);
            uint32_t a2 = *reinterpret_cast<const uint32_t*>(&qs[m + g    ][kc + 8]);
            uint32_t a3 = *reinterpret_cast<const uint32_t*>(&qs[m + g + 8][kc + 8]);
            #pragma unroll
            for (int nt = 0; nt < 4; nt++) {
                int n = (warp >> 2) * 32 + nt * 8;
                uint32_t b0 = *reinterpret_cast<const uint32_t*>(&ks[n + g][kc    ]);
                uint32_t b1 = *reinterpret_cast<const uint32_t*>(&ks[n + g][kc + 8]);
                mma_f16(acc[nt], a0, a1, a2, a3, b0, b1);
            }
        }
        #pragma unroll
        for (int nt = 0; nt < 4; nt++) {
            int row = (warp & 3) * 16 + g;
            int col = (warp >> 2) * 32 + nt * 8 + 2 * t4;
            *reinterpret_cast<float2*>(&sc[row][col])     = make_float2(acc[nt][0], acc[nt][1]);
            *reinterpret_cast<float2*>(&sc[row + 8][col]) = make_float2(acc[nt][2], acc[nt][3]);
        }
    }
    __syncthreads();

    // ---- softmax on the 49 live rows (scale applied here, f32)
    for (int r = warp; r < 49; r += 8) {
        float s0 = sc[r][lane] * scale;
        float s1 = sc[r][lane + 32] * scale;
        bool  v1 = (lane + 32) < 49;
        float mx = fmaxf(s0, v1 ? s1 : -1e30f);
        #pragma unroll
        for (int o = 16; o; o >>= 1) mx = fmaxf(mx, __shfl_xor_sync(0xffffffffu, mx, o));
        float e0 = __expf(s0 - mx);
        float e1 = v1 ? __expf(s1 - mx) : 0.f;
        float sm = e0 + e1;
        #pragma unroll
        for (int o = 16; o; o >>= 1) sm += __shfl_xor_sync(0xffffffffu, sm, o);
        float inv = 1.f / sm;
        ph[r][lane]      = __float2half(e0 * inv);
        ph[r][lane + 32] = __float2half(e1 * inv);
    }
    __syncthreads();

    // ---- out = P @ V  (64x32x64, fp16 mma, 4 k16 steps)
    {
        float acc[2][4];
        #pragma unroll
        for (int j = 0; j < 2; j++)
            #pragma unroll
            for (int k = 0; k < 4; k++) acc[j][k] = 0.f;

        const int m = (warp & 3) * 16;
        #pragma unroll
        for (int kq = 0; kq < 4; kq++) {
            int kc = kq * 16 + 2 * t4;
            uint32_t a0 = *reinterpret_cast<const uint32_t*>(&ph[m + g    ][kc    ]);
            uint32_t a1 = *reinterpret_cast<const uint32_t*>(&ph[m + g + 8][kc    ]);
            uint32_t a2 = *reinterpret_cast<const uint32_t*>(&ph[m + g    ][kc + 8]);
            uint32_t a3 = *reinterpret_cast<const uint32_t*>(&ph[m + g + 8][kc + 8]);
            #pragma unroll
            for (int j = 0; j < 2; j++) {
                int n = (warp >> 2) * 16 + j * 8;
                uint32_t b0 = *reinterpret_cast<const uint32_t*>(&vT[n + g][kc    ]);
                uint32_t b1 = *reinterpret_cast<const uint32_t*>(&vT[n + g][kc + 8]);
                mma_f16(acc[j], a0, a1, a2, a3, b0, b1);
            }
        }
        #pragma unroll
        for (int j = 0; j < 2; j++) {
            int col = (warp >> 2) * 16 + j * 8 + 2 * t4;
            #pragma unroll
            for (int i = 0; i < 2; i++) {
                int r = m + g + i * 8;
                if (r < 49) {
                    long off = (long)(w * 49 + r) * C_DIM + h * 32 + col;
                    *reinterpret_cast<__half2*>(g_att + off) =
                        __floats2half2_rn(acc[j][0 + 2 * i], acc[j][1 + 2 * i]);
                }
            }
        }
    }
}

// ---------------------------------------------------------------------------
extern "C" void kernel_launch(void* const* d_in, const int* in_sizes, int n_in,
                              void* d_out, int out_size)
{
    const float* x      = (const float*)d_in[0];
    const float* w_qkv  = (const float*)d_in[1];
    const float* w_proj = (const float*)d_in[2];
    const float* b_proj = (const float*)d_in[3];
    float* out = (float*)d_out;

    __half *xh, *wqkvh, *wprojh, *atth;
    cudaGetSymbolAddress((void**)&xh,     g_xh);
    cudaGetSymbolAddress((void**)&wqkvh,  g_wqkvh);
    cudaGetSymbolAddress((void**)&wprojh, g_wprojh);
    cudaGetSymbolAddress((void**)&atth,   g_att);

    cudaFuncSetAttribute(gemm_f16_kernel<1>,
                         cudaFuncAttributeMaxDynamicSharedMemorySize, SMEM_BYTES);
    cudaFuncSetAttribute(gemm_f16_kernel<2>,
                         cudaFuncAttributeMaxDynamicSharedMemorySize, SMEM_BYTES);

    // 0) f32 -> f16 prepass
    cvt_h_kernel<<<(M_TOK * C_DIM / 8 + 255) / 256, 256>>>(x, xh, M_TOK * C_DIM / 8);
    cvt_h_kernel<<<(QKV_DIM * C_DIM / 8 + 255) / 256, 256>>>(w_qkv, wqkvh, QKV_DIM * C_DIM / 8);
    cvt_h_kernel<<<(C_DIM * C_DIM / 8 + 255) / 256, 256>>>(w_proj, wprojh, C_DIM * C_DIM / 8);

    // 1) QKV projection (fp16 mma, 512 thr) -> window-major fp16 qkv
    gemm_f16_kernel<1><<<dim3(QKV_DIM / 128, M_TOK / 128), 512, SMEM_BYTES>>>(
        xh, wqkvh, nullptr, nullptr, QKV_DIM);

    // 2) Windowed attention (fp16 mma) -> fp16 window-major rows
    attn_kernel<<<dim3(12, 1024), 256>>>();

    // 3) Output projection (fp16 mma, 512 thr) + bias; rows -> token order
    gemm_f16_kernel<2><<<dim3(C_DIM / 128, M_TOK / 128), 512, SMEM_BYTES>>>(
        atth, wprojh, b_proj, out, C_DIM);
}

// round 15
// speedup vs baseline: 1.8138x; 1.1875x over previous
#include <cuda_runtime.h>
#include <cuda_fp16.h>
#include <cstdint>

// B=16, N=3136 (56x56), C=384, NH=12, hd=32, WS=7, nW=1024, S=49.
#define M_TOK   50176
#define C_DIM   384
#define QKV_DIM 1152
#define K_DIM   384

// Scratch (device globals: allocation-free)
static __device__ __half g_xh  [(size_t)M_TOK * C_DIM];
static __device__ __half g_wqkvh[QKV_DIM * C_DIM];
static __device__ __half g_wprojh[C_DIM * C_DIM];
// window-major qkv (fp16): ((w*3+qkv)*12+h)*1568 + s*32 + d
static __device__ __half g_qkvh[(size_t)M_TOK * QKV_DIM];
// window-major attn out (fp16): row = w*49+s, 384 cols
static __device__ __half g_att[(size_t)M_TOK * C_DIM];

__device__ __forceinline__ void mma_f16(float c[4],
                                        uint32_t a0, uint32_t a1, uint32_t a2, uint32_t a3,
                                        uint32_t b0, uint32_t b1) {
    asm volatile(
        "mma.sync.aligned.m16n8k16.row.col.f32.f16.f16.f32 "
        "{%0,%1,%2,%3}, {%4,%5,%6,%7}, {%8,%9}, {%0,%1,%2,%3};\n"
        : "+f"(c[0]), "+f"(c[1]), "+f"(c[2]), "+f"(c[3])
        : "r"(a0), "r"(a1), "r"(a2), "r"(a3), "r"(b0), "r"(b1));
}

__device__ __forceinline__ void ldm_x4(uint32_t& d0, uint32_t& d1, uint32_t& d2, uint32_t& d3,
                                       uint32_t addr) {
    asm volatile("ldmatrix.sync.aligned.m8n8.x4.shared.b16 {%0,%1,%2,%3}, [%4];"
                 : "=r"(d0), "=r"(d1), "=r"(d2), "=r"(d3) : "r"(addr));
}

__device__ __forceinline__ void cp16(uint32_t smem_addr, const void* gptr) {
    asm volatile("cp.async.cg.shared.global [%0], [%1], 16;\n"
                 :: "r"(smem_addr), "l"(gptr));
}

// ---------------------------------------------------------------------------
// Prepass: all three f32 -> f16 conversions in ONE launch.
// ---------------------------------------------------------------------------
#define N8_X  (M_TOK * C_DIM / 8)        // 2408448
#define N8_WQ (QKV_DIM * C_DIM / 8)      // 55296
#define N8_WP (C_DIM * C_DIM / 8)        // 18432
#define N8_ALL (N8_X + N8_WQ + N8_WP)

__global__ void cvt_all_kernel(const float* __restrict__ x,
                               const float* __restrict__ wq,
                               const float* __restrict__ wp,
                               __half* __restrict__ xh,
                               __half* __restrict__ wqh,
                               __half* __restrict__ wph)
{
    int i = blockIdx.x * blockDim.x + threadIdx.x;
    if (i >= N8_ALL) return;
    const float* src; __half* dst; int j;
    if (i < N8_X)              { src = x;  dst = xh;  j = i; }
    else if (i < N8_X + N8_WQ) { src = wq; dst = wqh; j = i - N8_X; }
    else                       { src = wp; dst = wph; j = i - N8_X - N8_WQ; }
    float4 v0 = reinterpret_cast<const float4*>(src)[2 * j];
    float4 v1 = reinterpret_cast<const float4*>(src)[2 * j + 1];
    __half2 h[4];
    h[0] = __floats2half2_rn(v0.x, v0.y);
    h[1] = __floats2half2_rn(v0.z, v0.w);
    h[2] = __floats2half2_rn(v1.x, v1.y);
    h[3] = __floats2half2_rn(v1.z, v1.w);
    reinterpret_cast<uint4*>(dst)[j] = *reinterpret_cast<uint4*>(h);
}

// ---------------------------------------------------------------------------
// fp16 GEMM (unchanged from R13): 512 threads, warp tile 32x32, BK=64,
// 3-stage cp.async, ldmatrix. MODE 1: scatter fp16 qkv. MODE 2: un-permute.
// ---------------------------------------------------------------------------
#define ROW_B    144
#define TILE_B   (128 * ROW_B)
#define STAGE_B  (2 * TILE_B)
#define SMEM_BYTES (3 * STAGE_B)

template<int MODE>
__global__ __launch_bounds__(512, 2) void gemm_f16_kernel(
    const __half* __restrict__ A, const __half* __restrict__ B,
    const float* __restrict__ bias, float* __restrict__ Cout, int N)
{
    extern __shared__ char smem[];

    const int tid  = threadIdx.x;
    const int lane = tid & 31;
    const int warp = tid >> 5;
    const int wm   = warp & 3;
    const int wn   = warp >> 2;
    const int g    = lane >> 2;
    const int t4   = lane & 3;

    const long bm = (long)blockIdx.y * 128;
    const long bn = (long)blockIdx.x * 128;

    const int lrow = tid >> 2;
    const int lcp  = (tid & 3) * 2;

    float acc[2][4][4];
    #pragma unroll
    for (int i = 0; i < 2; i++)
        #pragma unroll
        for (int j = 0; j < 4; j++)
            #pragma unroll
            for (int k = 0; k < 4; k++) acc[i][j][k] = 0.f;

    const __half* gA = A + (bm + lrow) * (long)K_DIM;
    const __half* gB = B + (bn + lrow) * (long)K_DIM;

    const uint32_t sbase = (uint32_t)__cvta_generic_to_shared(smem);

    auto issue = [&](int stg, int kb) {
        uint32_t dA = sbase + stg * STAGE_B;
        uint32_t dB = dA + TILE_B;
        #pragma unroll
        for (int c = 0; c < 2; c++) {
            uint32_t off = lrow * ROW_B + (lcp + c) * 16;
            cp16(dA + off, gA + kb + (lcp + c) * 8);
            cp16(dB + off, gB + kb + (lcp + c) * 8);
        }
        asm volatile("cp.async.commit_group;\n");
    };

    const int mi = lane >> 3, ri = lane & 7;
    const uint32_t aOff = (wm * 32 + ((mi & 1) << 3) + ri) * ROW_B + ((mi >> 1) << 4);
    uint32_t bOff[2];
    #pragma unroll
    for (int p = 0; p < 2; p++)
        bOff[p] = (wn * 32 + p * 16 + ((mi >> 1) << 3) + ri) * ROW_B + ((mi & 1) << 4);

    issue(0, 0);
    issue(1, 64);

    for (int k = 0; k < 6; k++) {
        if (k < 4) asm volatile("cp.async.wait_group 1;\n");
        else       asm volatile("cp.async.wait_group 0;\n");
        __syncthreads();

        if (k + 2 < 6) issue((k + 2) % 3, (k + 2) * 64);

        const uint32_t stA = sbase + (k % 3) * STAGE_B;
        const uint32_t stB = stA + TILE_B;

        #pragma unroll
        for (int kq = 0; kq < 4; kq++) {
            uint32_t a[2][4];
            #pragma unroll
            for (int mt = 0; mt < 2; mt++)
                ldm_x4(a[mt][0], a[mt][1], a[mt][2], a[mt][3],
                       stA + aOff + mt * (16 * ROW_B) + kq * 32);

            uint32_t bf[4][2];
            #pragma unroll
            for (int p = 0; p < 2; p++) {
                uint32_t d0, d1, d2, d3;
                ldm_x4(d0, d1, d2, d3, stB + bOff[p] + kq * 32);
                bf[2 * p    ][0] = d0; bf[2 * p    ][1] = d1;
                bf[2 * p + 1][0] = d2; bf[2 * p + 1][1] = d3;
            }

            #pragma unroll
            for (int mt = 0; mt < 2; mt++)
                #pragma unroll
                for (int nt = 0; nt < 4; nt++)
                    mma_f16(acc[mt][nt], a[mt][0], a[mt][1], a[mt][2], a[mt][3],
                            bf[nt][0], bf[nt][1]);
        }
    }

    #pragma unroll
    for (int mt = 0; mt < 2; mt++) {
        #pragma unroll
        for (int half_i = 0; half_i < 2; half_i++) {
            long row = bm + wm * 32 + mt * 16 + g + half_i * 8;

            if (MODE == 1) {
                int t  = (int)row;
                int b  = t / 3136;
                int r2 = t - b * 3136;
                int rr = r2 / 56;
                int cc = r2 - rr * 56;
                int w  = b * 64 + (rr / 7) * 8 + (cc / 7);
                int s  = (rr % 7) * 7 + (cc % 7);
                #pragma unroll
                for (int nt = 0; nt < 4; nt++) {
                    int col = (int)bn + wn * 32 + nt * 8 + 2 * t4;
                    int qkv = col / 384;
                    int rem = col - qkv * 384;
                    int h   = rem >> 5;
                    int d   = rem & 31;
                    long off = (long)((w * 3 + qkv) * 12 + h) * 1568 + s * 32 + d;
                    *reinterpret_cast<__half2*>(g_qkvh + off) =
                        __floats2half2_rn(acc[mt][nt][2 * half_i], acc[mt][nt][2 * half_i + 1]);
                }
            } else {
                int r = (int)row;
                int w = r / 49;
                int s = r - w * 49;
                int b  = w >> 6;
                int wh = (w >> 3) & 7;
                int ww = w & 7;
                long tok = (long)b * 3136 + (wh * 7 + s / 7) * 56 + ww * 7 + (s % 7);
                #pragma unroll
                for (int nt = 0; nt < 4; nt++) {
                    long col = bn + wn * 32 + nt * 8 + 2 * t4;
                    float2 bv = *reinterpret_cast<const float2*>(bias + col);
                    *reinterpret_cast<float2*>(Cout + tok * (long)N + col) =
                        make_float2(acc[mt][nt][2 * half_i] + bv.x,
                                    acc[mt][nt][2 * half_i + 1] + bv.y);
                }
            }
        }
    }
}

// ---------------------------------------------------------------------------
// Windowed attention, register-resident softmax. 2 windows per 256-thr CTA
// (warps 0-3 -> w0, warps 4-7 -> w1). Warp tile 16x64 for QK^T so each warp
// owns full score rows; softmax reduces over the 4-lane quad via shfl; P
// fragments are repacked in registers and fed straight to P@V. ONE barrier.
// ---------------------------------------------------------------------------
__global__ __launch_bounds__(256) void attn_kernel()
{
    __shared__ __half qs[2][64][40];
    __shared__ __half ks[2][64][40];
    __shared__ __half vT[2][32][72];

    const int tid  = threadIdx.x;
    const int lane = tid & 31;
    const int warp = tid >> 5;
    const int wi   = warp >> 2;         // window within pair
    const int wl   = warp & 3;          // warp within window (m-tile)
    const int g    = lane >> 2;
    const int t4   = lane & 3;

    const int h  = blockIdx.x;
    const int w0 = blockIdx.y * 2;
    const float scale = 0.17677669529663687f;   // 1/sqrt(32)

    // zero vT pad cols 49..63 (P=0 there, but smem garbage could be NaN)
    for (int i = tid; i < 2 * 32 * 15; i += 256) {
        int wz = i / (32 * 15);
        int r  = i - wz * (32 * 15);
        vT[wz][r / 15][49 + r % 15] = __ushort_as_half(0);
    }

    // coalesced loads: per window 196 uint4 slots per matrix
    for (int idx = tid; idx < 392; idx += 256) {
        int wz = idx >= 196;
        int j  = idx - 196 * wz;
        int s  = j >> 2, dd = (j & 3) << 3;
        const __half* base = g_qkvh + (long)(((w0 + wz) * 3) * 12 + h) * 1568;
        uint4 q4 = *reinterpret_cast<const uint4*>(base + j * 8);
        uint4 k4 = *reinterpret_cast<const uint4*>(base + 12 * 1568 + j * 8);
        uint4 v4 = *reinterpret_cast<const uint4*>(base + 24 * 1568 + j * 8);
        *reinterpret_cast<uint4*>(&qs[wz][s][dd]) = q4;
        *reinterpret_cast<uint4*>(&ks[wz][s][dd]) = k4;
        const __half* vh = reinterpret_cast<const __half*>(&v4);
        #pragma unroll
        for (int i = 0; i < 8; i++) vT[wz][dd + i][s] = vh[i];
    }
    __syncthreads();

    const int m = wl * 16;

    // ---- scores: warp computes rows m..m+15 x all 64 cols (8 nt, 2 kq)
    float acc[8][4];
    #pragma unroll
    for (int j = 0; j < 8; j++)
        #pragma unroll
        for (int k = 0; k < 4; k++) acc[j][k] = 0.f;

    #pragma unroll
    for (int kq = 0; kq < 2; kq++) {
        int kc = kq * 16 + 2 * t4;
        uint32_t a0 = *reinterpret_cast<const uint32_t*>(&qs[wi][m + g    ][kc    ]);
        uint32_t a1 = *reinterpret_cast<const uint32_t*>(&qs[wi][m + g + 8][kc    ]);
        uint32_t a2 = *reinterpret_cast<const uint32_t*>(&qs[wi][m + g    ][kc + 8]);
        uint32_t a3 = *reinterpret_cast<const uint32_t*>(&qs[wi][m + g + 8][kc + 8]);
        #pragma unroll
        for (int nt = 0; nt < 8; nt++) {
            int n = nt * 8;
            uint32_t b0 = *reinterpret_cast<const uint32_t*>(&ks[wi][n + g][kc    ]);
            uint32_t b1 = *reinterpret_cast<const uint32_t*>(&ks[wi][n + g][kc + 8]);
            mma_f16(acc[nt], a0, a1, a2, a3, b0, b1);
        }
    }

    // ---- register softmax: rows r0=m+g (c0,c1) and r1=m+g+8 (c2,c3)
    float mx0 = -1e30f, mx1 = -1e30f;
    #pragma unroll
    for (int nt = 0; nt < 8; nt++) {
        int col0 = nt * 8 + 2 * t4;
        acc[nt][0] = (col0     < 49) ? acc[nt][0] * scale : -1e30f;
        acc[nt][1] = (col0 + 1 < 49) ? acc[nt][1] * scale : -1e30f;
        acc[nt][2] = (col0     < 49) ? acc[nt][2] * scale : -1e30f;
        acc[nt][3] = (col0 + 1 < 49) ? acc[nt][3] * scale : -1e30f;
        mx0 = fmaxf(mx0, fmaxf(acc[nt][0], acc[nt][1]));
        mx1 = fmaxf(mx1, fmaxf(acc[nt][2], acc[nt][3]));
    }
    mx0 = fmaxf(mx0, __shfl_xor_sync(0xffffffffu, mx0, 1));
    mx0 = fmaxf(mx0, __shfl_xor_sync(0xffffffffu, mx0, 2));
    mx1 = fmaxf(mx1, __shfl_xor_sync(0xffffffffu, mx1, 1));
    mx1 = fmaxf(mx1, __shfl_xor_sync(0xffffffffu, mx1, 2));

    float sum0 = 0.f, sum1 = 0.f;
    #pragma unroll
    for (int nt = 0; nt < 8; nt++) {
        acc[nt][0] = __expf(acc[nt][0] - mx0);
        acc[nt][1] = __expf(acc[nt][1] - mx0);
        acc[nt][2] = __expf(acc[nt][2] - mx1);
        acc[nt][3] = __expf(acc[nt][3] - mx1);
        sum0 += acc[nt][0] + acc[nt][1];
        sum1 += acc[nt][2] + acc[nt][3];
    }
    sum0 += __shfl_xor_sync(0xffffffffu, sum0, 1);
    sum0 += __shfl_xor_sync(0xffffffffu, sum0, 2);
    sum1 += __shfl_xor_sync(0xffffffffu, sum1, 1);
    sum1 += __shfl_xor_sync(0xffffffffu, sum1, 2);
    const float inv0 = 1.f / sum0, inv1 = 1.f / sum1;

    // P fragments: p0[nt] = row r0 cols (nt*8+2t4, +1); p1[nt] = row r1
    uint32_t p0[8], p1[8];
    #pragma unroll
    for (int nt = 0; nt < 8; nt++) {
        __half2 h0 = __floats2half2_rn(acc[nt][0] * inv0, acc[nt][1] * inv0);
        __half2 h1 = __floats2half2_rn(acc[nt][2] * inv1, acc[nt][3] * inv1);
        p0[nt] = *reinterpret_cast<uint32_t*>(&h0);
        p1[nt] = *reinterpret_cast<uint32_t*>(&h1);
    }

    // ---- out = P @ V  (16x32x64: 4 kq x 4 nt2); A fragments from p0/p1
    float acc2[4][4];
    #pragma unroll
    for (int j = 0; j < 4; j++)
        #pragma unroll
        for (int k = 0; k < 4; k++) acc2[j][k] = 0.f;

    #pragma unroll
    for (int kq = 0; kq < 4; kq++) {
        uint32_t a0 = p0[2 * kq];
        uint32_t a1 = p1[2 * kq];
        uint32_t a2 = p0[2 * kq + 1];
        uint32_t a3 = p1[2 * kq + 1];
        int kc = kq * 16 + 2 * t4;
        #pragma unroll
        for (int nt2 = 0; nt2 < 4; nt2++) {
            int n = nt2 * 8;
            uint32_t b0 = *reinterpret_cast<const uint32_t*>(&vT[wi][n + g][kc    ]);
            uint32_t b1 = *reinterpret_cast<const uint32_t*>(&vT[wi][n + g][kc + 8]);
            mma_f16(acc2[nt2], a0, a1, a2, a3, b0, b1);
        }
    }

    // ---- store rows < 49
    const long wrow = (long)(w0 + wi) * 49;
    #pragma unroll
    for (int nt2 = 0; nt2 < 4; nt2++) {
        int col = nt2 * 8 + 2 * t4;
        int r0 = m + g, r1 = m + g + 8;
        if (r0 < 49)
            *reinterpret_cast<__half2*>(g_att + (wrow + r0) * C_DIM + h * 32 + col) =
                __floats2half2_rn(acc2[nt2][0], acc2[nt2][1]);
        if (r1 < 49)
            *reinterpret_cast<__half2*>(g_att + (wrow + r1) * C_DIM + h * 32 + col) =
                __floats2half2_rn(acc2[nt2][2], acc2[nt2][3]);
    }
}

// ---------------------------------------------------------------------------
extern "C" void kernel_launch(void* const* d_in, const int* in_sizes, int n_in,
                              void* d_out, int out_size)
{
    const float* x      = (const float*)d_in[0];
    const float* w_qkv  = (const float*)d_in[1];
    const float* w_proj = (const float*)d_in[2];
    const float* b_proj = (const float*)d_in[3];
    float* out = (float*)d_out;

    __half *xh, *wqkvh, *wprojh, *atth;
    cudaGetSymbolAddress((void**)&xh,     g_xh);
    cudaGetSymbolAddress((void**)&wqkvh,  g_wqkvh);
    cudaGetSymbolAddress((void**)&wprojh, g_wprojh);
    cudaGetSymbolAddress((void**)&atth,   g_att);

    cudaFuncSetAttribute(gemm_f16_kernel<1>,
                         cudaFuncAttributeMaxDynamicSharedMemorySize, SMEM_BYTES);
    cudaFuncSetAttribute(gemm_f16_kernel<2>,
                         cudaFuncAttributeMaxDynamicSharedMemorySize, SMEM_BYTES);

    // 0) single fused f32 -> f16 prepass
    cvt_all_kernel<<<(N8_ALL + 255) / 256, 256>>>(x, w_qkv, w_proj, xh, wqkvh, wprojh);

    // 1) QKV projection (fp16 mma, 512 thr) -> window-major fp16 qkv
    gemm_f16_kernel<1><<<dim3(QKV_DIM / 128, M_TOK / 128), 512, SMEM_BYTES>>>(
        xh, wqkvh, nullptr, nullptr, QKV_DIM);

    // 2) Windowed attention (register softmax, 2 windows/CTA)
    attn_kernel<<<dim3(12, 512), 256>>>();

    // 3) Output projection (fp16 mma, 512 thr) + bias; rows -> token order
    gemm_f16_kernel<2><<<dim3(C_DIM / 128, M_TOK / 128), 512, SMEM_BYTES>>>(
        atth, wprojh, b_proj, out, C_DIM);
}

// round 16
// speedup vs baseline: 1.8409x; 1.0149x over previous
#include <cuda_runtime.h>
#include <cuda_fp16.h>
#include <cstdint>

// B=16, N=3136 (56x56), C=384, NH=12, hd=32, WS=7, nW=1024, S=49.
#define M_TOK   50176
#define C_DIM   384
#define QKV_DIM 1152
#define K_DIM   384

// Scratch (device globals: allocation-free)
static __device__ __half g_xh  [(size_t)M_TOK * C_DIM];
static __device__ __half g_wqkvh[QKV_DIM * C_DIM];
static __device__ __half g_wprojh[C_DIM * C_DIM];
// window-major qkv (fp16): ((w*3+qkv)*12+h)*1568 + s*32 + d
static __device__ __half g_qkvh[(size_t)M_TOK * QKV_DIM];
// window-major attn out (fp16): row = w*49+s, 384 cols
static __device__ __half g_att[(size_t)M_TOK * C_DIM];

__device__ __forceinline__ void mma_f16(float c[4],
                                        uint32_t a0, uint32_t a1, uint32_t a2, uint32_t a3,
                                        uint32_t b0, uint32_t b1) {
    asm volatile(
        "mma.sync.aligned.m16n8k16.row.col.f32.f16.f16.f32 "
        "{%0,%1,%2,%3}, {%4,%5,%6,%7}, {%8,%9}, {%0,%1,%2,%3};\n"
        : "+f"(c[0]), "+f"(c[1]), "+f"(c[2]), "+f"(c[3])
        : "r"(a0), "r"(a1), "r"(a2), "r"(a3), "r"(b0), "r"(b1));
}

__device__ __forceinline__ void ldm_x4(uint32_t& d0, uint32_t& d1, uint32_t& d2, uint32_t& d3,
                                       uint32_t addr) {
    asm volatile("ldmatrix.sync.aligned.m8n8.x4.shared.b16 {%0,%1,%2,%3}, [%4];"
                 : "=r"(d0), "=r"(d1), "=r"(d2), "=r"(d3) : "r"(addr));
}

__device__ __forceinline__ void ldm_x4_trans(uint32_t& d0, uint32_t& d1, uint32_t& d2, uint32_t& d3,
                                             uint32_t addr) {
    asm volatile("ldmatrix.sync.aligned.m8n8.x4.trans.shared.b16 {%0,%1,%2,%3}, [%4];"
                 : "=r"(d0), "=r"(d1), "=r"(d2), "=r"(d3) : "r"(addr));
}

__device__ __forceinline__ void cp16(uint32_t smem_addr, const void* gptr) {
    asm volatile("cp.async.cg.shared.global [%0], [%1], 16;\n"
                 :: "r"(smem_addr), "l"(gptr));
}

// ---------------------------------------------------------------------------
// Prepass: all three f32 -> f16 conversions in ONE launch.
// Wq rows (qkv output dims 0..383) are pre-scaled by 1/sqrt(32) so the
// attention kernel needs no score scaling.
// ---------------------------------------------------------------------------
#define N8_X  (M_TOK * C_DIM / 8)
#define N8_WQ (QKV_DIM * C_DIM / 8)
#define N8_WP (C_DIM * C_DIM / 8)
#define N8_ALL (N8_X + N8_WQ + N8_WP)

__global__ void cvt_all_kernel(const float* __restrict__ x,
                               const float* __restrict__ wq,
                               const float* __restrict__ wp,
                               __half* __restrict__ xh,
                               __half* __restrict__ wqh,
                               __half* __restrict__ wph)
{
    int i = blockIdx.x * blockDim.x + threadIdx.x;
    if (i >= N8_ALL) return;
    const float* src; __half* dst; int j;
    float s = 1.f;
    if (i < N8_X)              { src = x;  dst = xh;  j = i; }
    else if (i < N8_X + N8_WQ) {
        src = wq; dst = wqh; j = i - N8_X;
        if ((j * 8) / C_DIM < 384) s = 0.17677669529663687f;   // q rows pre-scaled
    }
    else                       { src = wp; dst = wph; j = i - N8_X - N8_WQ; }
    float4 v0 = reinterpret_cast<const float4*>(src)[2 * j];
    float4 v1 = reinterpret_cast<const float4*>(src)[2 * j + 1];
    __half2 h[4];
    h[0] = __floats2half2_rn(v0.x * s, v0.y * s);
    h[1] = __floats2half2_rn(v0.z * s, v0.w * s);
    h[2] = __floats2half2_rn(v1.x * s, v1.y * s);
    h[3] = __floats2half2_rn(v1.z * s, v1.w * s);
    reinterpret_cast<uint4*>(dst)[j] = *reinterpret_cast<uint4*>(h);
}

// ---------------------------------------------------------------------------
// fp16 GEMM (unchanged): 512 threads, warp tile 32x32, BK=64,
// 3-stage cp.async, ldmatrix. MODE 1: scatter fp16 qkv. MODE 2: un-permute.
// ---------------------------------------------------------------------------
#define ROW_B    144
#define TILE_B   (128 * ROW_B)
#define STAGE_B  (2 * TILE_B)
#define SMEM_BYTES (3 * STAGE_B)

template<int MODE>
__global__ __launch_bounds__(512, 2) void gemm_f16_kernel(
    const __half* __restrict__ A, const __half* __restrict__ B,
    const float* __restrict__ bias, float* __restrict__ Cout, int N)
{
    extern __shared__ char smem[];

    const int tid  = threadIdx.x;
    const int lane = tid & 31;
    const int warp = tid >> 5;
    const int wm   = warp & 3;
    const int wn   = warp >> 2;
    const int g    = lane >> 2;
    const int t4   = lane & 3;

    const long bm = (long)blockIdx.y * 128;
    const long bn = (long)blockIdx.x * 128;

    const int lrow = tid >> 2;
    const int lcp  = (tid & 3) * 2;

    float acc[2][4][4];
    #pragma unroll
    for (int i = 0; i < 2; i++)
        #pragma unroll
        for (int j = 0; j < 4; j++)
            #pragma unroll
            for (int k = 0; k < 4; k++) acc[i][j][k] = 0.f;

    const __half* gA = A + (bm + lrow) * (long)K_DIM;
    const __half* gB = B + (bn + lrow) * (long)K_DIM;

    const uint32_t sbase = (uint32_t)__cvta_generic_to_shared(smem);

    auto issue = [&](int stg, int kb) {
        uint32_t dA = sbase + stg * STAGE_B;
        uint32_t dB = dA + TILE_B;
        #pragma unroll
        for (int c = 0; c < 2; c++) {
            uint32_t off = lrow * ROW_B + (lcp + c) * 16;
            cp16(dA + off, gA + kb + (lcp + c) * 8);
            cp16(dB + off, gB + kb + (lcp + c) * 8);
        }
        asm volatile("cp.async.commit_group;\n");
    };

    const int mi = lane >> 3, ri = lane & 7;
    const uint32_t aOff = (wm * 32 + ((mi & 1) << 3) + ri) * ROW_B + ((mi >> 1) << 4);
    uint32_t bOff[2];
    #pragma unroll
    for (int p = 0; p < 2; p++)
        bOff[p] = (wn * 32 + p * 16 + ((mi >> 1) << 3) + ri) * ROW_B + ((mi & 1) << 4);

    issue(0, 0);
    issue(1, 64);

    for (int k = 0; k < 6; k++) {
        if (k < 4) asm volatile("cp.async.wait_group 1;\n");
        else       asm volatile("cp.async.wait_group 0;\n");
        __syncthreads();

        if (k + 2 < 6) issue((k + 2) % 3, (k + 2) * 64);

        const uint32_t stA = sbase + (k % 3) * STAGE_B;
        const uint32_t stB = stA + TILE_B;

        #pragma unroll
        for (int kq = 0; kq < 4; kq++) {
            uint32_t a[2][4];
            #pragma unroll
            for (int mt = 0; mt < 2; mt++)
                ldm_x4(a[mt][0], a[mt][1], a[mt][2], a[mt][3],
                       stA + aOff + mt * (16 * ROW_B) + kq * 32);

            uint32_t bf[4][2];
            #pragma unroll
            for (int p = 0; p < 2; p++) {
                uint32_t d0, d1, d2, d3;
                ldm_x4(d0, d1, d2, d3, stB + bOff[p] + kq * 32);
                bf[2 * p    ][0] = d0; bf[2 * p    ][1] = d1;
                bf[2 * p + 1][0] = d2; bf[2 * p + 1][1] = d3;
            }

            #pragma unroll
            for (int mt = 0; mt < 2; mt++)
                #pragma unroll
                for (int nt = 0; nt < 4; nt++)
                    mma_f16(acc[mt][nt], a[mt][0], a[mt][1], a[mt][2], a[mt][3],
                            bf[nt][0], bf[nt][1]);
        }
    }

    #pragma unroll
    for (int mt = 0; mt < 2; mt++) {
        #pragma unroll
        for (int half_i = 0; half_i < 2; half_i++) {
            long row = bm + wm * 32 + mt * 16 + g + half_i * 8;

            if (MODE == 1) {
                int t  = (int)row;
                int b  = t / 3136;
                int r2 = t - b * 3136;
                int rr = r2 / 56;
                int cc = r2 - rr * 56;
                int w  = b * 64 + (rr / 7) * 8 + (cc / 7);
                int s  = (rr % 7) * 7 + (cc % 7);
                #pragma unroll
                for (int nt = 0; nt < 4; nt++) {
                    int col = (int)bn + wn * 32 + nt * 8 + 2 * t4;
                    int qkv = col / 384;
                    int rem = col - qkv * 384;
                    int h   = rem >> 5;
                    int d   = rem & 31;
                    long off = (long)((w * 3 + qkv) * 12 + h) * 1568 + s * 32 + d;
                    *reinterpret_cast<__half2*>(g_qkvh + off) =
                        __floats2half2_rn(acc[mt][nt][2 * half_i], acc[mt][nt][2 * half_i + 1]);
                }
            } else {
                int r = (int)row;
                int w = r / 49;
                int s = r - w * 49;
                int b  = w >> 6;
                int wh = (w >> 3) & 7;
                int ww = w & 7;
                long tok = (long)b * 3136 + (wh * 7 + s / 7) * 56 + ww * 7 + (s % 7);
                #pragma unroll
                for (int nt = 0; nt < 4; nt++) {
                    long col = bn + wn * 32 + nt * 8 + 2 * t4;
                    float2 bv = *reinterpret_cast<const float2*>(bias + col);
                    *reinterpret_cast<float2*>(Cout + tok * (long)N + col) =
                        make_float2(acc[mt][nt][2 * half_i] + bv.x,
                                    acc[mt][nt][2 * half_i + 1] + bv.y);
                }
            }
        }
    }
}

// ---------------------------------------------------------------------------
// Windowed attention, register softmax + ldmatrix.trans V (no transpose
// scatter). 2 windows per 256-thr CTA. Q pre-scaled via weights.
// ---------------------------------------------------------------------------
__global__ __launch_bounds__(256) void attn_kernel()
{
    __shared__ __half qs[2][64][40];
    __shared__ __half ks[2][64][40];
    __shared__ __half vs[2][64][40];   // V rows natural; rows 49..63 zeroed

    const int tid  = threadIdx.x;
    const int lane = tid & 31;
    const int warp = tid >> 5;
    const int wi   = warp >> 2;
    const int wl   = warp & 3;
    const int g    = lane >> 2;
    const int t4   = lane & 3;

    const int h  = blockIdx.x;
    const int w0 = blockIdx.y * 2;

    // zero vs pad rows 49..63 (P=0 there, but smem garbage could be NaN)
    {
        const uint4 z4 = make_uint4(0, 0, 0, 0);
        for (int i = tid; i < 2 * 15 * 5; i += 256) {
            int wz = i / 75;
            int r  = (i - wz * 75) / 5;
            int c4 = (i - wz * 75) % 5;
            *reinterpret_cast<uint4*>(&vs[wz][49 + r][c4 * 8]) = z4;
        }
    }

    // coalesced loads: per window 196 uint4 slots per matrix
    for (int idx = tid; idx < 392; idx += 256) {
        int wz = idx >= 196;
        int j  = idx - 196 * wz;
        int s  = j >> 2, dd = (j & 3) << 3;
        const __half* base = g_qkvh + (long)(((w0 + wz) * 3) * 12 + h) * 1568;
        *reinterpret_cast<uint4*>(&qs[wz][s][dd]) =
            *reinterpret_cast<const uint4*>(base + j * 8);
        *reinterpret_cast<uint4*>(&ks[wz][s][dd]) =
            *reinterpret_cast<const uint4*>(base + 12 * 1568 + j * 8);
        *reinterpret_cast<uint4*>(&vs[wz][s][dd]) =
            *reinterpret_cast<const uint4*>(base + 24 * 1568 + j * 8);
    }
    __syncthreads();

    const int m = wl * 16;

    // ---- scores: warp computes rows m..m+15 x all 64 cols (8 nt, 2 kq)
    float acc[8][4];
    #pragma unroll
    for (int j = 0; j < 8; j++)
        #pragma unroll
        for (int k = 0; k < 4; k++) acc[j][k] = 0.f;

    #pragma unroll
    for (int kq = 0; kq < 2; kq++) {
        int kc = kq * 16 + 2 * t4;
        uint32_t a0 = *reinterpret_cast<const uint32_t*>(&qs[wi][m + g    ][kc    ]);
        uint32_t a1 = *reinterpret_cast<const uint32_t*>(&qs[wi][m + g + 8][kc    ]);
        uint32_t a2 = *reinterpret_cast<const uint32_t*>(&qs[wi][m + g    ][kc + 8]);
        uint32_t a3 = *reinterpret_cast<const uint32_t*>(&qs[wi][m + g + 8][kc + 8]);
        #pragma unroll
        for (int nt = 0; nt < 8; nt++) {
            int n = nt * 8;
            uint32_t b0 = *reinterpret_cast<const uint32_t*>(&ks[wi][n + g][kc    ]);
            uint32_t b1 = *reinterpret_cast<const uint32_t*>(&ks[wi][n + g][kc + 8]);
            mma_f16(acc[nt], a0, a1, a2, a3, b0, b1);
        }
    }

    // ---- register softmax (scale already folded into Wq)
    float mx0 = -1e30f, mx1 = -1e30f;
    #pragma unroll
    for (int nt = 0; nt < 8; nt++) {
        int col0 = nt * 8 + 2 * t4;
        acc[nt][0] = (col0     < 49) ? acc[nt][0] : -1e30f;
        acc[nt][1] = (col0 + 1 < 49) ? acc[nt][1] : -1e30f;
        acc[nt][2] = (col0     < 49) ? acc[nt][2] : -1e30f;
        acc[nt][3] = (col0 + 1 < 49) ? acc[nt][3] : -1e30f;
        mx0 = fmaxf(mx0, fmaxf(acc[nt][0], acc[nt][1]));
        mx1 = fmaxf(mx1, fmaxf(acc[nt][2], acc[nt][3]));
    }
    mx0 = fmaxf(mx0, __shfl_xor_sync(0xffffffffu, mx0, 1));
    mx0 = fmaxf(mx0, __shfl_xor_sync(0xffffffffu, mx0, 2));
    mx1 = fmaxf(mx1, __shfl_xor_sync(0xffffffffu, mx1, 1));
    mx1 = fmaxf(mx1, __shfl_xor_sync(0xffffffffu, mx1, 2));

    float sum0 = 0.f, sum1 = 0.f;
    #pragma unroll
    for (int nt = 0; nt < 8; nt++) {
        acc[nt][0] = __expf(acc[nt][0] - mx0);
        acc[nt][1] = __expf(acc[nt][1] - mx0);
        acc[nt][2] = __expf(acc[nt][2] - mx1);
        acc[nt][3] = __expf(acc[nt][3] - mx1);
        sum0 += acc[nt][0] + acc[nt][1];
        sum1 += acc[nt][2] + acc[nt][3];
    }
    sum0 += __shfl_xor_sync(0xffffffffu, sum0, 1);
    sum0 += __shfl_xor_sync(0xffffffffu, sum0, 2);
    sum1 += __shfl_xor_sync(0xffffffffu, sum1, 1);
    sum1 += __shfl_xor_sync(0xffffffffu, sum1, 2);
    const float inv0 = 1.f / sum0, inv1 = 1.f / sum1;

    // P fragments: p0[nt] = row r0 cols (nt*8+2t4, +1); p1[nt] = row r1
    uint32_t p0[8], p1[8];
    #pragma unroll
    for (int nt = 0; nt < 8; nt++) {
        __half2 h0 = __floats2half2_rn(acc[nt][0] * inv0, acc[nt][1] * inv0);
        __half2 h1 = __floats2half2_rn(acc[nt][2] * inv1, acc[nt][3] * inv1);
        p0[nt] = *reinterpret_cast<uint32_t*>(&h0);
        p1[nt] = *reinterpret_cast<uint32_t*>(&h1);
    }

    // ---- out = P @ V  (16x32x64); B fragments via ldmatrix.x4.trans on vs
    float acc2[4][4];
    #pragma unroll
    for (int j = 0; j < 4; j++)
        #pragma unroll
        for (int k = 0; k < 4; k++) acc2[j][k] = 0.f;

    const int l8  = lane & 7;
    const int seg = lane >> 3;          // 0..3 -> (k-half, n-half)

    #pragma unroll
    for (int kq = 0; kq < 4; kq++) {
        uint32_t a0 = p0[2 * kq];
        uint32_t a1 = p1[2 * kq];
        uint32_t a2 = p0[2 * kq + 1];
        uint32_t a3 = p1[2 * kq + 1];
        #pragma unroll
        for (int p2 = 0; p2 < 2; p2++) {
            int krow = kq * 16 + (seg & 1) * 8 + l8;
            int ncol = p2 * 16 + (seg >> 1) * 8;
            uint32_t addr = (uint32_t)__cvta_generic_to_shared(&vs[wi][krow][ncol]);
            uint32_t b0, b1, b2, b3;
            ldm_x4_trans(b0, b1, b2, b3, addr);
            mma_f16(acc2[2 * p2    ], a0, a1, a2, a3, b0, b1);
            mma_f16(acc2[2 * p2 + 1], a0, a1, a2, a3, b2, b3);
        }
    }

    // ---- store rows < 49
    const long wrow = (long)(w0 + wi) * 49;
    #pragma unroll
    for (int nt2 = 0; nt2 < 4; nt2++) {
        int col = nt2 * 8 + 2 * t4;
        int r0 = m + g, r1 = m + g + 8;
        if (r0 < 49)
            *reinterpret_cast<__half2*>(g_att + (wrow + r0) * C_DIM + h * 32 + col) =
                __floats2half2_rn(acc2[nt2][0], acc2[nt2][1]);
        if (r1 < 49)
            *reinterpret_cast<__half2*>(g_att + (wrow + r1) * C_DIM + h * 32 + col) =
                __floats2half2_rn(acc2[nt2][2], acc2[nt2][3]);
    }
}

// ---------------------------------------------------------------------------
extern "C" void kernel_launch(void* const* d_in, const int* in_sizes, int n_in,
                              void* d_out, int out_size)
{
    const float* x      = (const float*)d_in[0];
    const float* w_qkv  = (const float*)d_in[1];
    const float* w_proj = (const float*)d_in[2];
    const float* b_proj = (const float*)d_in[3];
    float* out = (float*)d_out;

    __half *xh, *wqkvh, *wprojh, *atth;
    cudaGetSymbolAddress((void**)&xh,     g_xh);
    cudaGetSymbolAddress((void**)&wqkvh,  g_wqkvh);
    cudaGetSymbolAddress((void**)&wprojh, g_wprojh);
    cudaGetSymbolAddress((void**)&atth,   g_att);

    cudaFuncSetAttribute(gemm_f16_kernel<1>,
                         cudaFuncAttributeMaxDynamicSharedMemorySize, SMEM_BYTES);
    cudaFuncSetAttribute(gemm_f16_kernel<2>,
                         cudaFuncAttributeMaxDynamicSharedMemorySize, SMEM_BYTES);

    // 0) single fused f32 -> f16 prepass (q-weights pre-scaled)
    cvt_all_kernel<<<(N8_ALL + 255) / 256, 256>>>(x, w_qkv, w_proj, xh, wqkvh, wprojh);

    // 1) QKV projection (fp16 mma, 512 thr) -> window-major fp16 qkv
    gemm_f16_kernel<1><<<dim3(QKV_DIM / 128, M_TOK / 128), 512, SMEM_BYTES>>>(
        xh, wqkvh, nullptr, nullptr, QKV_DIM);

    // 2) Windowed attention (register softmax, ldmatrix.trans V)
    attn_kernel<<<dim3(12, 512), 256>>>();

    // 3) Output projection (fp16 mma, 512 thr) + bias; rows -> token order
    gemm_f16_kernel<2><<<dim3(C_DIM / 128, M_TOK / 128), 512, SMEM_BYTES>>>(
        atth, wprojh, b_proj, out, C_DIM);
}

// round 17
// speedup vs baseline: 2.0727x; 1.1259x over previous
#include <cuda_runtime.h>
#include <cuda_fp16.h>
#include <cuda.h>
#include <cstdint>

// B=16, N=3136 (56x56), C=384, NH=12, hd=32, WS=7, nW=1024, S=49.
#define M_TOK   50176
#define C_DIM   384
#define QKV_DIM 1152
#define K_DIM   384

// Scratch (device globals: allocation-free)
static __device__ __half g_xh  [(size_t)M_TOK * C_DIM];
static __device__ __half g_wqkvh[QKV_DIM * C_DIM];
static __device__ __half g_wprojh[C_DIM * C_DIM];
// window-major qkv (fp16): ((w*3+qkv)*12+h)*1568 + s*32 + d
static __device__ __half g_qkvh[(size_t)M_TOK * QKV_DIM];
// window-major attn out (fp16): row = w*49+s, 384 cols
static __device__ __half g_att[(size_t)M_TOK * C_DIM];

__device__ __forceinline__ void mma_f16(float c[4],
                                        uint32_t a0, uint32_t a1, uint32_t a2, uint32_t a3,
                                        uint32_t b0, uint32_t b1) {
    asm volatile(
        "mma.sync.aligned.m16n8k16.row.col.f32.f16.f16.f32 "
        "{%0,%1,%2,%3}, {%4,%5,%6,%7}, {%8,%9}, {%0,%1,%2,%3};\n"
        : "+f"(c[0]), "+f"(c[1]), "+f"(c[2]), "+f"(c[3])
        : "r"(a0), "r"(a1), "r"(a2), "r"(a3), "r"(b0), "r"(b1));
}

__device__ __forceinline__ void ldm_x4(uint32_t& d0, uint32_t& d1, uint32_t& d2, uint32_t& d3,
                                       uint32_t addr) {
    asm volatile("ldmatrix.sync.aligned.m8n8.x4.shared.b16 {%0,%1,%2,%3}, [%4];"
                 : "=r"(d0), "=r"(d1), "=r"(d2), "=r"(d3) : "r"(addr));
}

__device__ __forceinline__ void ldm_x4_trans(uint32_t& d0, uint32_t& d1, uint32_t& d2, uint32_t& d3,
                                             uint32_t addr) {
    asm volatile("ldmatrix.sync.aligned.m8n8.x4.trans.shared.b16 {%0,%1,%2,%3}, [%4];"
                 : "=r"(d0), "=r"(d1), "=r"(d2), "=r"(d3) : "r"(addr));
}

#define MBAR_INIT(a, c) \
    asm volatile("mbarrier.init.shared.b64 [%0], %1;" :: "r"(a), "r"(c) : "memory")
#define MBAR_EXPECT_TX(a, b) \
    asm volatile("mbarrier.arrive.expect_tx.shared.b64 _, [%0], %1;" :: "r"(a), "r"(b) : "memory")

__device__ __forceinline__ void mbar_wait(uint32_t mbar, uint32_t parity) {
    asm volatile(
        "{\n\t.reg .pred P1;\n\t"
        "WAIT_LOOP_%=:\n\t"
        "mbarrier.try_wait.parity.acquire.cta.shared::cta.b64 P1, [%0], %1, 0x989680;\n\t"
        "@P1 bra.uni WAIT_DONE_%=;\n\t"
        "bra.uni WAIT_LOOP_%=;\n\t"
        "WAIT_DONE_%=:\n\t}"
        :: "r"(mbar), "r"(parity) : "memory");
}

__device__ __forceinline__ void tma_load_2d(uint32_t smem_dst, const void* tmap,
                                            int cx, int cy, uint32_t mbar) {
    asm volatile(
        "cp.async.bulk.tensor.2d.shared::cta.global.tile.mbarrier::complete_tx::bytes "
        "[%0], [%1, {%2, %3}], [%4];"
        :: "r"(smem_dst), "l"(tmap), "r"(cx), "r"(cy), "r"(mbar) : "memory");
}

// ---------------------------------------------------------------------------
// Prepass: all three f32 -> f16 conversions in ONE launch (q-rows pre-scaled)
// ---------------------------------------------------------------------------
#define N8_X  (M_TOK * C_DIM / 8)
#define N8_WQ (QKV_DIM * C_DIM / 8)
#define N8_WP (C_DIM * C_DIM / 8)
#define N8_ALL (N8_X + N8_WQ + N8_WP)

__global__ void cvt_all_kernel(const float* __restrict__ x,
                               const float* __restrict__ wq,
                               const float* __restrict__ wp,
                               __half* __restrict__ xh,
                               __half* __restrict__ wqh,
                               __half* __restrict__ wph)
{
    int i = blockIdx.x * blockDim.x + threadIdx.x;
    if (i >= N8_ALL) return;
    const float* src; __half* dst; int j;
    float s = 1.f;
    if (i < N8_X)              { src = x;  dst = xh;  j = i; }
    else if (i < N8_X + N8_WQ) {
        src = wq; dst = wqh; j = i - N8_X;
        if ((j * 8) / C_DIM < 384) s = 0.17677669529663687f;
    }
    else                       { src = wp; dst = wph; j = i - N8_X - N8_WQ; }
    float4 v0 = reinterpret_cast<const float4*>(src)[2 * j];
    float4 v1 = reinterpret_cast<const float4*>(src)[2 * j + 1];
    __half2 h[4];
    h[0] = __floats2half2_rn(v0.x * s, v0.y * s);
    h[1] = __floats2half2_rn(v0.z * s, v0.w * s);
    h[2] = __floats2half2_rn(v1.x * s, v1.y * s);
    h[3] = __floats2half2_rn(v1.z * s, v1.w * s);
    reinterpret_cast<uint4*>(dst)[j] = *reinterpret_cast<uint4*>(h);
}

// ---------------------------------------------------------------------------
// TMA fp16 GEMM: C[m,n] = sum_k A[m,k]*B[n,k]. 512 threads, warp tile 32x32,
// BM=BN=128, BK=64. 3-stage TMA pipeline (one bulk-tensor load pair per
// stage, mbarrier expect_tx), SW128-swizzled smem, ldmatrix fragments.
// MODE 1: scatter fp16 qkv. MODE 2: un-permute rows + bias.
// smem: [0:24) mbars, [1024 + s*32768) stages (A 16KB then B 16KB).
// ---------------------------------------------------------------------------
#define TSTAGE_B   32768
#define TSMEM_TOT  (1024 + 3 * TSTAGE_B)

template<int MODE>
__global__ __launch_bounds__(512, 2) void gemm_f16_tma(
    const __grid_constant__ CUtensorMap tmA,
    const __grid_constant__ CUtensorMap tmB,
    const float* __restrict__ bias, float* __restrict__ Cout, int N)
{
    extern __shared__ __align__(1024) char smem[];
    const uint32_t sbase = (uint32_t)__cvta_generic_to_shared(smem);

    const int tid  = threadIdx.x;
    const int lane = tid & 31;
    const int warp = tid >> 5;
    const int wm   = warp & 3;          // 0..3 along M (32 rows)
    const int wn   = warp >> 2;         // 0..3 along N (32 cols)
    const int g    = lane >> 2;
    const int t4   = lane & 3;

    const int bm = blockIdx.y * 128;
    const int bn = blockIdx.x * 128;

    float acc[2][4][4];
    #pragma unroll
    for (int i = 0; i < 2; i++)
        #pragma unroll
        for (int j = 0; j < 4; j++)
            #pragma unroll
            for (int k = 0; k < 4; k++) acc[i][j][k] = 0.f;

    // mbarrier init + first two stage loads
    if (tid == 0) {
        #pragma unroll
        for (int s = 0; s < 3; s++) MBAR_INIT(sbase + 8 * s, 1);
    }
    __syncthreads();
    if (tid == 0) {
        #pragma unroll
        for (int s = 0; s < 2; s++) {
            uint32_t st = sbase + 1024 + s * TSTAGE_B;
            MBAR_EXPECT_TX(sbase + 8 * s, (uint32_t)TSTAGE_B);
            tma_load_2d(st,         &tmA, s * 64, bm, sbase + 8 * s);
            tma_load_2d(st + 16384, &tmB, s * 64, bn, sbase + 8 * s);
        }
    }

    // per-thread ldmatrix addressing (SW128 rows of 128B = 64 halfs)
    const int mi = lane >> 3, ri = lane & 7;
    const uint32_t rx = (uint32_t)ri << 4;               // (row&7)*16
    const int rA0 = wm * 32 + ((mi & 1) << 3) + ri;
    const int cA  = (mi >> 1) << 4;                      // byte col base
    const int cB  = (mi & 1) << 4;
    uint32_t aRow[2];
    #pragma unroll
    for (int mt = 0; mt < 2; mt++) aRow[mt] = (uint32_t)(rA0 + mt * 16) * 128;
    uint32_t bRow[2];
    #pragma unroll
    for (int p = 0; p < 2; p++)
        bRow[p] = (uint32_t)(wn * 32 + p * 16 + ((mi >> 1) << 3) + ri) * 128;

    for (int k = 0; k < 6; k++) {
        mbar_wait(sbase + 8 * (k % 3), (k / 3) & 1);
        __syncthreads();

        if (tid == 0 && k + 2 < 6) {
            int s = (k + 2) % 3;
            uint32_t st = sbase + 1024 + s * TSTAGE_B;
            MBAR_EXPECT_TX(sbase + 8 * s, (uint32_t)TSTAGE_B);
            tma_load_2d(st,         &tmA, (k + 2) * 64, bm, sbase + 8 * s);
            tma_load_2d(st + 16384, &tmB, (k + 2) * 64, bn, sbase + 8 * s);
        }

        const uint32_t stA = sbase + 1024 + (k % 3) * TSTAGE_B;
        const uint32_t stB = stA + 16384;

        #pragma unroll
        for (int kq = 0; kq < 4; kq++) {
            const uint32_t swA = (uint32_t)(kq * 32 + cA) ^ rx;
            const uint32_t swB = (uint32_t)(kq * 32 + cB) ^ rx;

            uint32_t a[2][4];
            #pragma unroll
            for (int mt = 0; mt < 2; mt++)
                ldm_x4(a[mt][0], a[mt][1], a[mt][2], a[mt][3], stA + aRow[mt] + swA);

            uint32_t bf[4][2];
            #pragma unroll
            for (int p = 0; p < 2; p++) {
                uint32_t d0, d1, d2, d3;
                ldm_x4(d0, d1, d2, d3, stB + bRow[p] + swB);
                bf[2 * p    ][0] = d0; bf[2 * p    ][1] = d1;
                bf[2 * p + 1][0] = d2; bf[2 * p + 1][1] = d3;
            }

            #pragma unroll
            for (int mt = 0; mt < 2; mt++)
                #pragma unroll
                for (int nt = 0; nt < 4; nt++)
                    mma_f16(acc[mt][nt], a[mt][0], a[mt][1], a[mt][2], a[mt][3],
                            bf[nt][0], bf[nt][1]);
        }
    }

    // ---- epilogue (unchanged) ----
    #pragma unroll
    for (int mt = 0; mt < 2; mt++) {
        #pragma unroll
        for (int half_i = 0; half_i < 2; half_i++) {
            long row = (long)bm + wm * 32 + mt * 16 + g + half_i * 8;

            if (MODE == 1) {
                int t  = (int)row;
                int b  = t / 3136;
                int r2 = t - b * 3136;
                int rr = r2 / 56;
                int cc = r2 - rr * 56;
                int w  = b * 64 + (rr / 7) * 8 + (cc / 7);
                int s  = (rr % 7) * 7 + (cc % 7);
                #pragma unroll
                for (int nt = 0; nt < 4; nt++) {
                    int col = bn + wn * 32 + nt * 8 + 2 * t4;
                    int qkv = col / 384;
                    int rem = col - qkv * 384;
                    int h   = rem >> 5;
                    int d   = rem & 31;
                    long off = (long)((w * 3 + qkv) * 12 + h) * 1568 + s * 32 + d;
                    *reinterpret_cast<__half2*>(g_qkvh + off) =
                        __floats2half2_rn(acc[mt][nt][2 * half_i], acc[mt][nt][2 * half_i + 1]);
                }
            } else {
                int r = (int)row;
                int w = r / 49;
                int s = r - w * 49;
                int b  = w >> 6;
                int wh = (w >> 3) & 7;
                int ww = w & 7;
                long tok = (long)b * 3136 + (wh * 7 + s / 7) * 56 + ww * 7 + (s % 7);
                #pragma unroll
                for (int nt = 0; nt < 4; nt++) {
                    long col = bn + wn * 32 + nt * 8 + 2 * t4;
                    float2 bv = *reinterpret_cast<const float2*>(bias + col);
                    *reinterpret_cast<float2*>(Cout + tok * (long)N + col) =
                        make_float2(acc[mt][nt][2 * half_i] + bv.x,
                                    acc[mt][nt][2 * half_i + 1] + bv.y);
                }
            }
        }
    }
}

// ---------------------------------------------------------------------------
// Windowed attention (unchanged from R16): register softmax + ldmatrix.trans V
// ---------------------------------------------------------------------------
__global__ __launch_bounds__(256) void attn_kernel()
{
    __shared__ __half qs[2][64][40];
    __shared__ __half ks[2][64][40];
    __shared__ __half vs[2][64][40];

    const int tid  = threadIdx.x;
    const int lane = tid & 31;
    const int warp = tid >> 5;
    const int wi   = warp >> 2;
    const int wl   = warp & 3;
    const int g    = lane >> 2;
    const int t4   = lane & 3;

    const int h  = blockIdx.x;
    const int w0 = blockIdx.y * 2;

    {
        const uint4 z4 = make_uint4(0, 0, 0, 0);
        for (int i = tid; i < 2 * 15 * 5; i += 256) {
            int wz = i / 75;
            int r  = (i - wz * 75) / 5;
            int c4 = (i - wz * 75) % 5;
            *reinterpret_cast<uint4*>(&vs[wz][49 + r][c4 * 8]) = z4;
        }
    }

    for (int idx = tid; idx < 392; idx += 256) {
        int wz = idx >= 196;
        int j  = idx - 196 * wz;
        int s  = j >> 2, dd = (j & 3) << 3;
        const __half* base = g_qkvh + (long)(((w0 + wz) * 3) * 12 + h) * 1568;
        *reinterpret_cast<uint4*>(&qs[wz][s][dd]) =
            *reinterpret_cast<const uint4*>(base + j * 8);
        *reinterpret_cast<uint4*>(&ks[wz][s][dd]) =
            *reinterpret_cast<const uint4*>(base + 12 * 1568 + j * 8);
        *reinterpret_cast<uint4*>(&vs[wz][s][dd]) =
            *reinterpret_cast<const uint4*>(base + 24 * 1568 + j * 8);
    }
    __syncthreads();

    const int m = wl * 16;

    float acc[8][4];
    #pragma unroll
    for (int j = 0; j < 8; j++)
        #pragma unroll
        for (int k = 0; k < 4; k++) acc[j][k] = 0.f;

    #pragma unroll
    for (int kq = 0; kq < 2; kq++) {
        int kc = kq * 16 + 2 * t4;
        uint32_t a0 = *reinterpret_cast<const uint32_t*>(&qs[wi][m + g    ][kc    ]);
        uint32_t a1 = *reinterpret_cast<const uint32_t*>(&qs[wi][m + g + 8][kc    ]);
        uint32_t a2 = *reinterpret_cast<const uint32_t*>(&qs[wi][m + g    ][kc + 8]);
        uint32_t a3 = *reinterpret_cast<const uint32_t*>(&qs[wi][m + g + 8][kc + 8]);
        #pragma unroll
        for (int nt = 0; nt < 8; nt++) {
            int n = nt * 8;
            uint32_t b0 = *reinterpret_cast<const uint32_t*>(&ks[wi][n + g][kc    ]);
            uint32_t b1 = *reinterpret_cast<const uint32_t*>(&ks[wi][n + g][kc + 8]);
            mma_f16(acc[nt], a0, a1, a2, a3, b0, b1);
        }
    }

    float mx0 = -1e30f, mx1 = -1e30f;
    #pragma unroll
    for (int nt = 0; nt < 8; nt++) {
        int col0 = nt * 8 + 2 * t4;
        acc[nt][0] = (col0     < 49) ? acc[nt][0] : -1e30f;
        acc[nt][1] = (col0 + 1 < 49) ? acc[nt][1] : -1e30f;
        acc[nt][2] = (col0     < 49) ? acc[nt][2] : -1e30f;
        acc[nt][3] = (col0 + 1 < 49) ? acc[nt][3] : -1e30f;
        mx0 = fmaxf(mx0, fmaxf(acc[nt][0], acc[nt][1]));
        mx1 = fmaxf(mx1, fmaxf(acc[nt][2], acc[nt][3]));
    }
    mx0 = fmaxf(mx0, __shfl_xor_sync(0xffffffffu, mx0, 1));
    mx0 = fmaxf(mx0, __shfl_xor_sync(0xffffffffu, mx0, 2));
    mx1 = fmaxf(mx1, __shfl_xor_sync(0xffffffffu, mx1, 1));
    mx1 = fmaxf(mx1, __shfl_xor_sync(0xffffffffu, mx1, 2));

    float sum0 = 0.f, sum1 = 0.f;
    #pragma unroll
    for (int nt = 0; nt < 8; nt++) {
        acc[nt][0] = __expf(acc[nt][0] - mx0);
        acc[nt][1] = __expf(acc[nt][1] - mx0);
        acc[nt][2] = __expf(acc[nt][2] - mx1);
        acc[nt][3] = __expf(acc[nt][3] - mx1);
        sum0 += acc[nt][0] + acc[nt][1];
        sum1 += acc[nt][2] + acc[nt][3];
    }
    sum0 += __shfl_xor_sync(0xffffffffu, sum0, 1);
    sum0 += __shfl_xor_sync(0xffffffffu, sum0, 2);
    sum1 += __shfl_xor_sync(0xffffffffu, sum1, 1);
    sum1 += __shfl_xor_sync(0xffffffffu, sum1, 2);
    const float inv0 = 1.f / sum0, inv1 = 1.f / sum1;

    uint32_t p0[8], p1[8];
    #pragma unroll
    for (int nt = 0; nt < 8; nt++) {
        __half2 h0 = __floats2half2_rn(acc[nt][0] * inv0, acc[nt][1] * inv0);
        __half2 h1 = __floats2half2_rn(acc[nt][2] * inv1, acc[nt][3] * inv1);
        p0[nt] = *reinterpret_cast<uint32_t*>(&h0);
        p1[nt] = *reinterpret_cast<uint32_t*>(&h1);
    }

    float acc2[4][4];
    #pragma unroll
    for (int j = 0; j < 4; j++)
        #pragma unroll
        for (int k = 0; k < 4; k++) acc2[j][k] = 0.f;

    const int l8  = lane & 7;
    const int seg = lane >> 3;

    #pragma unroll
    for (int kq = 0; kq < 4; kq++) {
        uint32_t a0 = p0[2 * kq];
        uint32_t a1 = p1[2 * kq];
        uint32_t a2 = p0[2 * kq + 1];
        uint32_t a3 = p1[2 * kq + 1];
        #pragma unroll
        for (int p2 = 0; p2 < 2; p2++) {
            int krow = kq * 16 + (seg & 1) * 8 + l8;
            int ncol = p2 * 16 + (seg >> 1) * 8;
            uint32_t addr = (uint32_t)__cvta_generic_to_shared(&vs[wi][krow][ncol]);
            uint32_t b0, b1, b2, b3;
            ldm_x4_trans(b0, b1, b2, b3, addr);
            mma_f16(acc2[2 * p2    ], a0, a1, a2, a3, b0, b1);
            mma_f16(acc2[2 * p2 + 1], a0, a1, a2, a3, b2, b3);
        }
    }

    const long wrow = (long)(w0 + wi) * 49;
    #pragma unroll
    for (int nt2 = 0; nt2 < 4; nt2++) {
        int col = nt2 * 8 + 2 * t4;
        int r0 = m + g, r1 = m + g + 8;
        if (r0 < 49)
            *reinterpret_cast<__half2*>(g_att + (wrow + r0) * C_DIM + h * 32 + col) =
                __floats2half2_rn(acc2[nt2][0], acc2[nt2][1]);
        if (r1 < 49)
            *reinterpret_cast<__half2*>(g_att + (wrow + r1) * C_DIM + h * 32 + col) =
                __floats2half2_rn(acc2[nt2][2], acc2[nt2][3]);
    }
}

// ---------------------------------------------------------------------------
// Host side: tensor-map construction via cudart driver-entry-point (no -lcuda)
// ---------------------------------------------------------------------------
typedef CUresult (*EncodeFn)(CUtensorMap*, CUtensorMapDataType, cuuint32_t, void*,
                             const cuuint64_t*, const cuuint64_t*,
                             const cuuint32_t*, const cuuint32_t*,
                             CUtensorMapInterleave, CUtensorMapSwizzle,
                             CUtensorMapL2promotion, CUtensorMapFloatOOBfill);

static void make_map(EncodeFn enc, CUtensorMap* tm, void* ptr, uint64_t rows) {
    cuuint64_t dims[2]    = {(cuuint64_t)K_DIM, (cuuint64_t)rows};
    cuuint64_t strides[1] = {(cuuint64_t)K_DIM * 2};
    cuuint32_t box[2]     = {64, 128};
    cuuint32_t estr[2]    = {1, 1};
    enc(tm, CU_TENSOR_MAP_DATA_TYPE_FLOAT16, 2, ptr, dims, strides, box, estr,
        CU_TENSOR_MAP_INTERLEAVE_NONE, CU_TENSOR_MAP_SWIZZLE_128B,
        CU_TENSOR_MAP_L2_PROMOTION_L2_128B, CU_TENSOR_MAP_FLOAT_OOB_FILL_NONE);
}

extern "C" void kernel_launch(void* const* d_in, const int* in_sizes, int n_in,
                              void* d_out, int out_size)
{
    const float* x      = (const float*)d_in[0];
    const float* w_qkv  = (const float*)d_in[1];
    const float* w_proj = (const float*)d_in[2];
    const float* b_proj = (const float*)d_in[3];
    float* out = (float*)d_out;

    __half *xh, *wqkvh, *wprojh, *atth;
    cudaGetSymbolAddress((void**)&xh,     g_xh);
    cudaGetSymbolAddress((void**)&wqkvh,  g_wqkvh);
    cudaGetSymbolAddress((void**)&wprojh, g_wprojh);
    cudaGetSymbolAddress((void**)&atth,   g_att);

    EncodeFn enc = nullptr;
    cudaDriverEntryPointQueryResult qr;
    cudaGetDriverEntryPoint("cuTensorMapEncodeTiled", (void**)&enc,
                            cudaEnableDefault, &qr);

    CUtensorMap tmA1, tmB1, tmA3, tmB3;
    make_map(enc, &tmA1, xh,     M_TOK);
    make_map(enc, &tmB1, wqkvh,  QKV_DIM);
    make_map(enc, &tmA3, atth,   M_TOK);
    make_map(enc, &tmB3, wprojh, C_DIM);

    cudaFuncSetAttribute(gemm_f16_tma<1>,
                         cudaFuncAttributeMaxDynamicSharedMemorySize, TSMEM_TOT);
    cudaFuncSetAttribute(gemm_f16_tma<2>,
                         cudaFuncAttributeMaxDynamicSharedMemorySize, TSMEM_TOT);

    // 0) single fused f32 -> f16 prepass (q-weights pre-scaled)
    cvt_all_kernel<<<(N8_ALL + 255) / 256, 256>>>(x, w_qkv, w_proj, xh, wqkvh, wprojh);

    // 1) QKV projection (TMA + fp16 mma) -> window-major fp16 qkv
    gemm_f16_tma<1><<<dim3(QKV_DIM / 128, M_TOK / 128), 512, TSMEM_TOT>>>(
        tmA1, tmB1, nullptr, nullptr, QKV_DIM);

    // 2) Windowed attention (register softmax, ldmatrix.trans V)
    attn_kernel<<<dim3(12, 512), 256>>>();

    // 3) Output projection (TMA + fp16 mma) + bias; rows -> token order
    gemm_f16_tma<2><<<dim3(C_DIM / 128, M_TOK / 128), 512, TSMEM_TOT>>>(
        tmA3, tmB3, b_proj, out, C_DIM);
}